// round 15
// baseline (speedup 1.0000x reference)
#include <cuda_runtime.h>
#include <cuda_bf16.h>
#include <cuda_fp16.h>
#include <math.h>
#include <stdint.h>

#define HIDDEN 1024
#define NHEADS 16
#define HDIM   64
#define BB     4
#define SSEQ   1024
#define MTOT   (BB*SSEQ)   // 4096

// ---------------- persistent buffers (device globals) -----------------------
#define BIG (MTOT*HIDDEN)
__device__ __align__(16) __half g_xh16[BIG], g_xl16[BIG];
__device__ __align__(16) __nv_bfloat16 g_qh[BIG],  g_ql[BIG];
__device__ __align__(16) __nv_bfloat16 g_kh[BIG],  g_kl[BIG];
__device__ __align__(16) __half g_Wqf[HIDDEN*HIDDEN];
__device__ __align__(16) __half g_Wkf[HIDDEN*HIDDEN];
__device__ __align__(16) __half g_Wvf[HIDDEN*HIDDEN];
__device__ __align__(16) __half g_spkf[BIG];
__device__ __align__(16) __half g_vf[BIG];
__device__ __align__(16) __half g_mpf[BIG];
__device__ __align__(16) __half g_ctxf[BIG];
__device__ __align__(16) __half g_cgf[BIG];
__device__ __align__(16) __half g_Wgf[2*HIDDEN*HIDDEN];
__device__ __align__(16) __half g_Wof[HIDDEN*HIDDEN];
__device__ float g_ctx[BIG];
__device__ __align__(16) float g_vsum[BB*NHEADS*16*HDIM];

__device__ __forceinline__ float sigmoidf_(float x) {
    return 1.0f / (1.0f + __expf(-x));
}
__device__ __forceinline__ uint32_t smem_to_u32(const void* p) {
    uint32_t a;
    asm("{ .reg .u64 t; cvta.to.shared.u64 t, %1; cvt.u32.u64 %0, t; }"
        : "=r"(a) : "l"(p));
    return a;
}

// ---------------- async copy helpers ----------------------------------------
__device__ __forceinline__ void cp16(uint32_t dst, const void* src) {
    asm volatile("cp.async.cg.shared.global [%0], [%1], 16;" :: "r"(dst), "l"(src));
}
__device__ __forceinline__ void cp_commit() {
    asm volatile("cp.async.commit_group;" ::: "memory");
}
template<int N> __device__ __forceinline__ void cp_wait() {
    asm volatile("cp.async.wait_group %0;" :: "n"(N) : "memory");
}

// ---------------- mma.sync helpers ------------------------------------------
__device__ __forceinline__ void ldsm_x4(uint32_t (&r)[4], uint32_t addr) {
    asm volatile("ldmatrix.sync.aligned.m8n8.x4.shared.b16 {%0,%1,%2,%3}, [%4];"
        : "=r"(r[0]), "=r"(r[1]), "=r"(r[2]), "=r"(r[3]) : "r"(addr));
}
__device__ __forceinline__ void ldsm_x4_trans(uint32_t (&r)[4], uint32_t addr) {
    asm volatile("ldmatrix.sync.aligned.m8n8.x4.trans.shared.b16 {%0,%1,%2,%3}, [%4];"
        : "=r"(r[0]), "=r"(r[1]), "=r"(r[2]), "=r"(r[3]) : "r"(addr));
}
__device__ __forceinline__ void mma_bf16(float (&d)[4], const uint32_t (&a)[4],
                                         const uint32_t* b) {
    asm volatile("mma.sync.aligned.m16n8k16.row.col.f32.bf16.bf16.f32 "
        "{%0,%1,%2,%3}, {%4,%5,%6,%7}, {%8,%9}, {%0,%1,%2,%3};"
        : "+f"(d[0]), "+f"(d[1]), "+f"(d[2]), "+f"(d[3])
        : "r"(a[0]), "r"(a[1]), "r"(a[2]), "r"(a[3]), "r"(b[0]), "r"(b[1]));
}
__device__ __forceinline__ void mma_f16(float (&d)[4], const uint32_t (&a)[4],
                                        const uint32_t* b) {
    asm volatile("mma.sync.aligned.m16n8k16.row.col.f32.f16.f16.f32 "
        "{%0,%1,%2,%3}, {%4,%5,%6,%7}, {%8,%9}, {%0,%1,%2,%3};"
        : "+f"(d[0]), "+f"(d[1]), "+f"(d[2]), "+f"(d[3])
        : "r"(a[0]), "r"(a[1]), "r"(a[2]), "r"(a[3]), "r"(b[0]), "r"(b[1]));
}
__device__ __forceinline__ uint32_t mul_bf16x2(uint32_t a, uint32_t b) {
    uint32_t d;
    asm("mul.rn.bf16x2 %0, %1, %2;" : "=r"(d) : "r"(a), "r"(b));
    return d;
}
__device__ __forceinline__ uint32_t mul_f16x2(uint32_t a, uint32_t b) {
    uint32_t d;
    asm("mul.rn.f16x2 %0, %1, %2;" : "=r"(d) : "r"(a), "r"(b));
    return d;
}
__device__ __forceinline__ void split2pack(float x, float y, uint32_t& hi, uint32_t& lo) {
    __nv_bfloat16 hx = __float2bfloat16_rn(x);
    __nv_bfloat16 hy = __float2bfloat16_rn(y);
    __nv_bfloat16 lx = __float2bfloat16_rn(x - __bfloat162float(hx));
    __nv_bfloat16 ly = __float2bfloat16_rn(y - __bfloat162float(hy));
    hi = (uint32_t)__bfloat16_as_ushort(hx) | ((uint32_t)__bfloat16_as_ushort(hy) << 16);
    lo = (uint32_t)__bfloat16_as_ushort(lx) | ((uint32_t)__bfloat16_as_ushort(ly) << 16);
}
__device__ __forceinline__ void split2pack_f16(float x, float y, uint32_t& hi, uint32_t& lo) {
    __half hx = __float2half_rn(x);
    __half hy = __float2half_rn(y);
    __half lx = __float2half_rn(x - __half2float(hx));
    __half ly = __float2half_rn(y - __half2float(hy));
    hi = (uint32_t)__half_as_ushort(hx) | ((uint32_t)__half_as_ushort(hy) << 16);
    lo = (uint32_t)__half_as_ushort(lx) | ((uint32_t)__half_as_ushort(ly) << 16);
}
__device__ __forceinline__ uint32_t packh2(float x, float y) {
    __half2 h = __floats2half2_rn(x, y);
    return *(uint32_t*)&h;
}

// ---------------- fused prep: all converts in ONE launch ---------------------
#define N4X (BIG/4)
#define N4W (HIDDEN*HIDDEN/4)
#define N4G (2*HIDDEN*HIDDEN/4)
#define N4TOT (3*N4X + 4*N4W + N4G)

__device__ __forceinline__ void cvt4(const float* src, __half* dst, int i) {
    float4 v = ((const float4*)src)[i];
    ((__half2*)dst)[i*2]     = __floats2half2_rn(v.x, v.y);
    ((__half2*)dst)[i*2 + 1] = __floats2half2_rn(v.z, v.w);
}

__global__ __launch_bounds__(256) void prep_all(
    const float* __restrict__ x,  const float* __restrict__ spk,
    const float* __restrict__ mp, const float* __restrict__ Wq,
    const float* __restrict__ Wk, const float* __restrict__ Wv,
    const float* __restrict__ Wo, const float* __restrict__ Wg,
    __half* __restrict__ xh,  __half* __restrict__ xl,
    __half* __restrict__ spkf, __half* __restrict__ mpf,
    __half* __restrict__ Wqf, __half* __restrict__ Wkf,
    __half* __restrict__ Wvf, __half* __restrict__ Wof,
    __half* __restrict__ Wgf)
{
    int i = blockIdx.x * blockDim.x + threadIdx.x;
    if (i >= N4TOT) return;
    if (i < N4X) {
        float4 v = ((const float4*)x)[i];
        uint2 hi, lo;
        split2pack_f16(v.x, v.y, hi.x, lo.x);
        split2pack_f16(v.z, v.w, hi.y, lo.y);
        ((uint2*)xh)[i] = hi;
        ((uint2*)xl)[i] = lo;
        return;
    }
    i -= N4X;
    if (i < N4X) { cvt4(spk, spkf, i); return; }
    i -= N4X;
    if (i < N4X) { cvt4(mp, mpf, i); return; }
    i -= N4X;
    if (i < N4W) { cvt4(Wq, Wqf, i); return; }
    i -= N4W;
    if (i < N4W) { cvt4(Wk, Wkf, i); return; }
    i -= N4W;
    if (i < N4W) { cvt4(Wv, Wvf, i); return; }
    i -= N4W;
    if (i < N4W) { cvt4(Wo, Wof, i); return; }
    i -= N4W;
    cvt4(Wg, Wgf, i);
}

// ---------------- per-(b,h,ktile) gated-V column sums (fp16 V) ---------------
__global__ __launch_bounds__(64) void vsum_kernel(
    const __half* __restrict__ vf_g, float* __restrict__ vsum)
{
    const int d = threadIdx.x;
    const int t = blockIdx.x, h = blockIdx.y, b = blockIdx.z;
    const size_t base = ((size_t)(b * SSEQ + t * 64)) * HIDDEN + h * HDIM + d;
    float s = 0.0f;
#pragma unroll 8
    for (int r = 0; r < 64; ++r)
        s += __half2float(vf_g[base + (size_t)r * HIDDEN]);
    vsum[(((size_t)b * NHEADS + h) * 16 + t) * HDIM + d] = s;
}

// ---------------------------------------------------------------------------
// Fused QKV projection GEMM: ONE launch, gridDim.z = 3 (0:Q, 1:K, 2:V).
// Q/K: fp16 2-term.  V: fp16 1-term.  3-stage cp.async, 2 CTAs/SM.
// ---------------------------------------------------------------------------
#define BKP      40
#define ARR_B    (128*BKP*2)          // 10240
#define STAGE_Q  (3*ARR_B)            // 30720
#define GEMMQ_SMEM (3*STAGE_Q)        // 92160

__global__ __launch_bounds__(256, 2) void gemm_qkv_fused(
    const __half* __restrict__ Ah_g, const __half* __restrict__ Al_g,
    const __half* __restrict__ WqB, const __half* __restrict__ WkB,
    const __half* __restrict__ WvB,
    const float* __restrict__ bq, const float* __restrict__ bk,
    const float* __restrict__ bv, const float* __restrict__ mpE,
    __nv_bfloat16* __restrict__ qh_o, __nv_bfloat16* __restrict__ ql_o,
    __nv_bfloat16* __restrict__ kh_o, __nv_bfloat16* __restrict__ kl_o,
    __half* __restrict__ vf_o)
{
    extern __shared__ __align__(128) char smem[];
    const uint32_t sbase = smem_to_u32(smem);
    const int tid = threadIdx.x, wid = tid >> 5, lane = tid & 31;
    const int m0 = blockIdx.y * 128, n0 = blockIdx.x * 128;
    const int z = blockIdx.z;
    const int K = HIDDEN, N = HIDDEN;
    const int NCH = K >> 5;

    const __half* Bm   = (z == 0) ? WqB : (z == 1) ? WkB : WvB;
    const float*  bias = (z == 0) ? bq  : (z == 1) ? bk  : bv;
    const bool two_term = (z != 2);

    const int wm = (wid >> 1) * 32;
    const int wn = (wid & 1) * 64;

    float acc[2][8][4];
#pragma unroll
    for (int mt = 0; mt < 2; mt++)
#pragma unroll
        for (int nt = 0; nt < 8; nt++)
#pragma unroll
            for (int j = 0; j < 4; j++) acc[mt][nt][j] = 0.0f;

    auto fill = [&](int c) {
        const uint32_t st = sbase + (uint32_t)(c % 3) * STAGE_Q;
        const int k0 = c * 32;
#pragma unroll
        for (int i = 0; i < 2; ++i) {
            const int s = tid + i * 256;
            const int row = s >> 2, q = s & 3;
            const uint32_t d = st + (uint32_t)(row * 80 + q * 16);
            const size_t ga = ((size_t)(m0 + row) * K + k0 + q * 8) * 2;
            cp16(d,           (const char*)Ah_g + ga);
            if (two_term) cp16(d + ARR_B, (const char*)Al_g + ga);
            const size_t gb = ((size_t)(n0 + row) * K + k0 + q * 8) * 2;
            cp16(d + 2*ARR_B, (const char*)Bm + gb);
        }
        cp_commit();
    };

    const uint32_t a_lane_off = (uint32_t)((lane & 15) * (BKP * 2) + (lane >> 4) * 16);
    const uint32_t b_lane_off = (uint32_t)(((lane & 7) + ((lane >> 4) << 3)) * (BKP * 2)
                                           + ((lane >> 3) & 1) * 16);

    auto compute_chunk = [&](int c) {
        const uint32_t b = sbase + (uint32_t)(c % 3) * STAGE_Q;
#pragma unroll
        for (int ks = 0; ks < 2; ++ks) {
            const uint32_t koffb = (uint32_t)(ks * 32);
            uint32_t ah[2][4], al[2][4];
#pragma unroll
            for (int mt = 0; mt < 2; ++mt) {
                const uint32_t off = (uint32_t)((wm + mt * 16) * (BKP * 2)) + a_lane_off + koffb;
                ldsm_x4(ah[mt], b + off);
                if (two_term) ldsm_x4(al[mt], b + ARR_B + off);
            }
            uint32_t bh[8][2];
#pragma unroll
            for (int np = 0; np < 4; ++np) {
                const uint32_t off = (uint32_t)((wn + np * 16) * (BKP * 2)) + b_lane_off + koffb;
                uint32_t r4[4];
                ldsm_x4(r4, b + 2*ARR_B + off);
                bh[np*2][0] = r4[0]; bh[np*2][1] = r4[1];
                bh[np*2+1][0] = r4[2]; bh[np*2+1][1] = r4[3];
            }
#pragma unroll
            for (int mt = 0; mt < 2; ++mt)
#pragma unroll
                for (int nt = 0; nt < 8; ++nt) {
                    mma_f16(acc[mt][nt], ah[mt], bh[nt]);
                    if (two_term) mma_f16(acc[mt][nt], al[mt], bh[nt]);
                }
        }
    };

    fill(0);
    fill(1);
    for (int c = 0; c < NCH; ++c) {
        if (c < NCH - 1) cp_wait<1>(); else cp_wait<0>();
        __syncthreads();
        if (c + 2 < NCH) fill(c + 2);
        compute_chunk(c);
    }

    __nv_bfloat16* Ch = (z == 0) ? qh_o : kh_o;
    __nv_bfloat16* Cl = (z == 0) ? ql_o : kl_o;

#pragma unroll
    for (int mt = 0; mt < 2; ++mt) {
        const int m = m0 + wm + mt * 16 + (lane >> 2);
#pragma unroll
        for (int nt = 0; nt < 8; ++nt) {
            const int n = n0 + wn + nt * 8 + (lane & 3) * 2;
            const float2 bv2 = *(const float2*)(bias + n);
#pragma unroll
            for (int half = 0; half < 2; ++half) {
                const size_t off = (size_t)(m + half * 8) * N + n;
                float v0 = acc[mt][nt][half*2 + 0] + bv2.x;
                float v1 = acc[mt][nt][half*2 + 1] + bv2.y;
                if (z == 2) {
                    float2 e = *(const float2*)(mpE + off);
                    v0 *= sigmoidf_(e.x); v1 *= sigmoidf_(e.y);
                    *(uint32_t*)((char*)vf_o + off * 2) = packh2(v0, v1);
                } else {
                    uint32_t hi, lo;
                    split2pack(v0, v1, hi, lo);
                    *(uint32_t*)((char*)Ch + off * 2) = hi;
                    *(uint32_t*)((char*)Cl + off * 2) = lo;
                }
            }
        }
    }
}

// ---------------------------------------------------------------------------
// Single-pass fp16 NT GEMM (gate + output), 3-stage, 2 CTAs/SM.
// ---------------------------------------------------------------------------
#define STAGE_H  (2*ARR_B)            // 20480
#define GEMMH_SMEM (3*STAGE_H)        // 61440

template<int EPI>
__global__ __launch_bounds__(256, 2) void gemm_h(
    const __half* __restrict__ A1, const __half* __restrict__ A2,
    int K1, int K,
    const __half* __restrict__ Bm,
    const float* __restrict__ bias, const float* __restrict__ E,
    float* __restrict__ C, __half* __restrict__ Cf,
    int M, int N)
{
    extern __shared__ __align__(128) char smem[];
    const uint32_t sbase = smem_to_u32(smem);
    const int tid = threadIdx.x, wid = tid >> 5, lane = tid & 31;
    const int m0 = blockIdx.y * 128, n0 = blockIdx.x * 128;
    const int NCH = K >> 5;

    const int wm = (wid >> 1) * 32;
    const int wn = (wid & 1) * 64;

    float acc[2][8][4];
#pragma unroll
    for (int mt = 0; mt < 2; mt++)
#pragma unroll
        for (int nt = 0; nt < 8; nt++)
#pragma unroll
            for (int j = 0; j < 4; j++) acc[mt][nt][j] = 0.0f;

    auto fill = [&](int c) {
        const uint32_t st = sbase + (uint32_t)(c % 3) * STAGE_H;
        const int k0 = c * 32;
        const __half* Ap; int lda, koff;
        if (k0 < K1) { Ap = A1; lda = K1;     koff = k0; }
        else         { Ap = A2; lda = K - K1; koff = k0 - K1; }
#pragma unroll
        for (int i = 0; i < 2; ++i) {
            const int s = tid + i * 256;
            const int row = s >> 2, q = s & 3;
            const uint32_t d = st + (uint32_t)(row * 80 + q * 16);
            const size_t ga = ((size_t)(m0 + row) * lda + koff + q * 8) * 2;
            cp16(d,           (const char*)Ap + ga);
            const size_t gb = ((size_t)(n0 + row) * K + k0 + q * 8) * 2;
            cp16(d + ARR_B,   (const char*)Bm + gb);
        }
        cp_commit();
    };

    const uint32_t a_lane_off = (uint32_t)((lane & 15) * (BKP * 2) + (lane >> 4) * 16);
    const uint32_t b_lane_off = (uint32_t)(((lane & 7) + ((lane >> 4) << 3)) * (BKP * 2)
                                           + ((lane >> 3) & 1) * 16);

    auto compute_chunk = [&](int c) {
        const uint32_t b = sbase + (uint32_t)(c % 3) * STAGE_H;
#pragma unroll
        for (int ks = 0; ks < 2; ++ks) {
            const uint32_t koffb = (uint32_t)(ks * 32);
            uint32_t ah[2][4];
#pragma unroll
            for (int mt = 0; mt < 2; ++mt) {
                const uint32_t off = (uint32_t)((wm + mt * 16) * (BKP * 2)) + a_lane_off + koffb;
                ldsm_x4(ah[mt], b + off);
            }
            uint32_t bh[8][2];
#pragma unroll
            for (int np = 0; np < 4; ++np) {
                const uint32_t off = (uint32_t)((wn + np * 16) * (BKP * 2)) + b_lane_off + koffb;
                uint32_t r4[4];
                ldsm_x4(r4, b + ARR_B + off);
                bh[np*2][0] = r4[0]; bh[np*2][1] = r4[1];
                bh[np*2+1][0] = r4[2]; bh[np*2+1][1] = r4[3];
            }
#pragma unroll
            for (int mt = 0; mt < 2; ++mt)
#pragma unroll
                for (int nt = 0; nt < 8; ++nt)
                    mma_f16(acc[mt][nt], ah[mt], bh[nt]);
        }
    };

    fill(0);
    fill(1);
    for (int c = 0; c < NCH; ++c) {
        if (c < NCH - 1) cp_wait<1>(); else cp_wait<0>();
        __syncthreads();
        if (c + 2 < NCH) fill(c + 2);
        compute_chunk(c);
    }

#pragma unroll
    for (int mt = 0; mt < 2; ++mt) {
        const int m = m0 + wm + mt * 16 + (lane >> 2);
#pragma unroll
        for (int nt = 0; nt < 8; ++nt) {
            const int n = n0 + wn + nt * 8 + (lane & 3) * 2;
            const float2 bv = *(const float2*)(bias + n);
#pragma unroll
            for (int half = 0; half < 2; ++half) {
                const size_t off = (size_t)(m + half * 8) * N + n;
                float v0 = acc[mt][nt][half*2 + 0] + bv.x;
                float v1 = acc[mt][nt][half*2 + 1] + bv.y;
                if (EPI == 2) {
                    float2 e = *(const float2*)(E + off);
                    v0 = e.x * sigmoidf_(v0); v1 = e.y * sigmoidf_(v1);
                    *(__half2*)(Cf + off) = __floats2half2_rn(v0, v1);
                } else {
                    *(float2*)(C + off) = make_float2(v0, v1);
                }
            }
        }
    }
}

// ---------------------------------------------------------------------------
// Tensor-core flash attention, decay-window tile skipping (dt<96).
// Mask exps via geometric recurrence: e^{-|d|/tau} = min(u, v), u/v geometric
// along the nt loop (step e^{+-8/tau}); 4 expf seeds per thread per tile
// instead of 32.
// ---------------------------------------------------------------------------
#define KROW    144
#define ARR_A   (64*KROW)              // 9216
#define STAGE_A (4*ARR_A)              // 36864
#define ATTN_SMEM (3*STAGE_A)          // 110592
#define SCALE2  0x3E003E00u            // bf16x2 {0.125, 0.125}
#define HSCALE2 0x30003000u            // f16x2  {0.125, 0.125}

__global__ __launch_bounds__(256, 1) void attn_mma(
    const __nv_bfloat16* __restrict__ qh_g, const __nv_bfloat16* __restrict__ ql_g,
    const __nv_bfloat16* __restrict__ kh_g, const __nv_bfloat16* __restrict__ kl_g,
    const __half* __restrict__ vf_g, const __half* __restrict__ skf_g,
    const float* __restrict__ tau, const float* __restrict__ vsum,
    float* __restrict__ ctx, __half* __restrict__ ctxf)
{
    extern __shared__ __align__(128) char smem[];
    const uint32_t sb = smem_to_u32(smem);
    const int tid = threadIdx.x, wid = tid >> 5, lane = tid & 31;
    const int lane4 = lane & 3, laneq = lane >> 2;
    const int h = blockIdx.y, b = blockIdx.z;
    const int q0 = blockIdx.x * 128;
    const float inv_tau = 1.0f / tau[h];
    const float r8  = __expf(8.0f * inv_tau);
    const float r8i = __expf(-8.0f * inv_tau);
    const float e1  = __expf(inv_tau);
    const float e1i = __expf(-inv_tau);

    const int lo = q0 - 158;
    const int ktmin = lo <= 0 ? 0 : ((lo + 63) >> 6);
    const int ktmax_ = (q0 + 222) >> 6;
    const int ktmax = ktmax_ > 15 ? 15 : ktmax_;

    const int ti0 = q0 + wid * 16 + laneq;
    const int ti1 = ti0 + 8;
    const size_t r0b = (size_t)(b * SSEQ + ti0) * HIDDEN + h * HDIM;
    const size_t r1b = (size_t)(b * SSEQ + ti1) * HIDDEN + h * HDIM;

    uint32_t qh[4][4], ql[4][4], sqf[4][4];
    {
        const char* qhp = (const char*)qh_g;
        const char* qlp = (const char*)ql_g;
        const char* sfp = (const char*)skf_g;
#pragma unroll
        for (int ks = 0; ks < 4; ++ks) {
            const int kc = ks * 16 + lane4 * 2;
            const size_t o00 = (r0b + kc) * 2, o10 = (r1b + kc) * 2;
            const size_t o01 = o00 + 16,       o11 = o10 + 16;
            qh[ks][0] = mul_bf16x2(*(const uint32_t*)(qhp + o00), SCALE2);
            qh[ks][1] = mul_bf16x2(*(const uint32_t*)(qhp + o10), SCALE2);
            qh[ks][2] = mul_bf16x2(*(const uint32_t*)(qhp + o01), SCALE2);
            qh[ks][3] = mul_bf16x2(*(const uint32_t*)(qhp + o11), SCALE2);
            ql[ks][0] = mul_bf16x2(*(const uint32_t*)(qlp + o00), SCALE2);
            ql[ks][1] = mul_bf16x2(*(const uint32_t*)(qlp + o10), SCALE2);
            ql[ks][2] = mul_bf16x2(*(const uint32_t*)(qlp + o01), SCALE2);
            ql[ks][3] = mul_bf16x2(*(const uint32_t*)(qlp + o11), SCALE2);
            sqf[ks][0] = mul_f16x2(*(const uint32_t*)(sfp + o00), HSCALE2);
            sqf[ks][1] = mul_f16x2(*(const uint32_t*)(sfp + o10), HSCALE2);
            sqf[ks][2] = mul_f16x2(*(const uint32_t*)(sfp + o01), HSCALE2);
            sqf[ks][3] = mul_f16x2(*(const uint32_t*)(sfp + o11), HSCALE2);
        }
    }

    float m0r = -1e30f, m1r = -1e30f, l0r = 0.0f, l1r = 0.0f;
    float o[8][4];
#pragma unroll
    for (int nt = 0; nt < 8; nt++)
#pragma unroll
        for (int j = 0; j < 4; j++) o[nt][j] = 0.0f;

    auto fill_tile = [&](int kt) {
        const uint32_t st = sb + (uint32_t)(kt % 3) * STAGE_A;
        const size_t base = ((size_t)(b * SSEQ + kt * 64)) * HIDDEN + h * HDIM;
#pragma unroll
        for (int i = 0; i < 2; ++i) {
            const int s = tid + i * 256;
            const int row = s >> 3, q = s & 7;
            const size_t g2 = (base + (size_t)row * HIDDEN + q * 8) * 2;
            const uint32_t d = st + (uint32_t)(row * KROW + q * 16);
            cp16(d + 0*ARR_A, (const char*)kh_g  + g2);
            cp16(d + 1*ARR_A, (const char*)kl_g  + g2);
            cp16(d + 2*ARR_A, (const char*)skf_g + g2);
            cp16(d + 3*ARR_A, (const char*)vf_g  + g2);
        }
        cp_commit();
    };

    const uint32_t b_off = (uint32_t)(((lane & 7) + ((lane >> 4) << 3)) * KROW
                                      + ((lane >> 3) & 1) * 16);
    const uint32_t v_off = (uint32_t)(((lane & 7) + ((lane >> 3) & 1) * 8) * KROW
                                      + ((lane >> 4) & 1) * 16);
    const float ti0f = (float)ti0, ti1f = (float)ti1;

    fill_tile(ktmin);
    if (ktmin + 1 <= ktmax) fill_tile(ktmin + 1);
    for (int kt = ktmin; kt <= ktmax; ++kt) {
        if (kt < ktmax) cp_wait<1>(); else cp_wait<0>();
        __syncthreads();
        if (kt + 2 <= ktmax) fill_tile(kt + 2);

        const uint32_t st = sb + (uint32_t)(kt % 3) * STAGE_A;
        const int k0 = kt * 64;

        float s[8][4], sp[8][4];
#pragma unroll
        for (int nt = 0; nt < 8; nt++)
#pragma unroll
            for (int j = 0; j < 4; j++) { s[nt][j] = 0.0f; sp[nt][j] = 0.0f; }

#pragma unroll
        for (int ks = 0; ks < 4; ++ks) {
            const uint32_t kb = (uint32_t)(ks * 32);
#pragma unroll
            for (int n8 = 0; n8 < 4; ++n8) {
                const uint32_t off = (uint32_t)(n8 * 16 * KROW) + b_off + kb;
                uint32_t rh[4], rl[4];
                ldsm_x4(rh, st + 0*ARR_A + off);
                ldsm_x4(rl, st + 1*ARR_A + off);
                mma_bf16(s[2*n8],   qh[ks], &rh[0]);
                mma_bf16(s[2*n8],   qh[ks], &rl[0]);
                mma_bf16(s[2*n8],   ql[ks], &rh[0]);
                mma_bf16(s[2*n8+1], qh[ks], &rh[2]);
                mma_bf16(s[2*n8+1], qh[ks], &rl[2]);
                mma_bf16(s[2*n8+1], ql[ks], &rh[2]);
                uint32_t rs[4];
                ldsm_x4(rs, st + 2*ARR_A + off);
                mma_f16(sp[2*n8],   sqf[ks], &rs[0]);
                mma_f16(sp[2*n8+1], sqf[ks], &rs[2]);
            }
        }

        // ---- mask via geometric recurrence + online softmax ----
        {
            const float d00 = (float)(k0 + lane4 * 2) - ti0f;   // tj(nt=0,col0) - ti0
            const float d10 = (float)(k0 + lane4 * 2) - ti1f;
            float u0 = __expf(d00 * inv_tau), v0 = __expf(-d00 * inv_tau);
            float u1 = __expf(d10 * inv_tau), v1 = __expf(-d10 * inv_tau);
            float u0b = u0 * e1, v0b = v0 * e1i;
            float u1b = u1 * e1, v1b = v1 * e1i;
            float rmax0 = -1e30f, rmax1 = -1e30f;
#pragma unroll
            for (int nt = 0; nt < 8; ++nt) {
                const float e00 = fminf(u0, v0);
                const float e01 = fminf(u0b, v0b);
                const float e10 = fminf(u1, v1);
                const float e11 = fminf(u1b, v1b);
                u0 *= r8; v0 *= r8i; u0b *= r8; v0b *= r8i;
                u1 *= r8; v1 *= r8i; u1b *= r8; v1b *= r8i;
                s[nt][0] = s[nt][0] * e00 * (1.0f + sp[nt][0]);
                s[nt][1] = s[nt][1] * e01 * (1.0f + sp[nt][1]);
                s[nt][2] = s[nt][2] * e10 * (1.0f + sp[nt][2]);
                s[nt][3] = s[nt][3] * e11 * (1.0f + sp[nt][3]);
                rmax0 = fmaxf(rmax0, fmaxf(s[nt][0], s[nt][1]));
                rmax1 = fmaxf(rmax1, fmaxf(s[nt][2], s[nt][3]));
            }
            rmax0 = fmaxf(rmax0, __shfl_xor_sync(0xffffffffu, rmax0, 1));
            rmax0 = fmaxf(rmax0, __shfl_xor_sync(0xffffffffu, rmax0, 2));
            rmax1 = fmaxf(rmax1, __shfl_xor_sync(0xffffffffu, rmax1, 1));
            rmax1 = fmaxf(rmax1, __shfl_xor_sync(0xffffffffu, rmax1, 2));
            const float mn0 = fmaxf(m0r, rmax0), mn1 = fmaxf(m1r, rmax1);
            const float c0 = __expf(m0r - mn0), c1 = __expf(m1r - mn1);
            float ls0 = 0.0f, ls1 = 0.0f;
#pragma unroll
            for (int nt = 0; nt < 8; ++nt) {
                float p;
                p = __expf(s[nt][0] - mn0); s[nt][0] = p; ls0 += p;
                p = __expf(s[nt][1] - mn0); s[nt][1] = p; ls0 += p;
                p = __expf(s[nt][2] - mn1); s[nt][2] = p; ls1 += p;
                p = __expf(s[nt][3] - mn1); s[nt][3] = p; ls1 += p;
            }
            ls0 += __shfl_xor_sync(0xffffffffu, ls0, 1);
            ls0 += __shfl_xor_sync(0xffffffffu, ls0, 2);
            ls1 += __shfl_xor_sync(0xffffffffu, ls1, 1);
            ls1 += __shfl_xor_sync(0xffffffffu, ls1, 2);
            l0r = l0r * c0 + ls0;  m0r = mn0;
            l1r = l1r * c1 + ls1;  m1r = mn1;
#pragma unroll
            for (int nt = 0; nt < 8; ++nt) {
                o[nt][0] *= c0; o[nt][1] *= c0;
                o[nt][2] *= c1; o[nt][3] *= c1;
            }
        }

#pragma unroll
        for (int ks = 0; ks < 4; ++ks) {
            uint32_t ph[4];
            ph[0] = packh2(s[2*ks][0],   s[2*ks][1]);
            ph[1] = packh2(s[2*ks][2],   s[2*ks][3]);
            ph[2] = packh2(s[2*ks+1][0], s[2*ks+1][1]);
            ph[3] = packh2(s[2*ks+1][2], s[2*ks+1][3]);
            const uint32_t roff = (uint32_t)(ks * 16 * KROW) + v_off;
#pragma unroll
            for (int n8 = 0; n8 < 4; ++n8) {
                uint32_t vfr[4];
                ldsm_x4_trans(vfr, st + 3*ARR_A + roff + (uint32_t)(n8 * 32));
                mma_f16(o[2*n8],   ph, &vfr[0]);
                mma_f16(o[2*n8+1], ph, &vfr[2]);
            }
        }
    }

    {
        float2 fsum[8];
#pragma unroll
        for (int nt = 0; nt < 8; ++nt) { fsum[nt].x = 0.0f; fsum[nt].y = 0.0f; }
        const float2* vsbase = (const float2*)(vsum + (((size_t)b * NHEADS + h) * 16) * HDIM);
        for (int t = 0; t < 16; ++t) {
            if (t >= ktmin && t <= ktmax) continue;
            const float2* vs = vsbase + t * (HDIM / 2);
#pragma unroll
            for (int nt = 0; nt < 8; ++nt) {
                float2 v = vs[nt * 4 + lane4];
                fsum[nt].x += v.x; fsum[nt].y += v.y;
            }
        }
        const float nfar = (float)(64 * (16 - (ktmax - ktmin + 1)));
        const float mf0 = fmaxf(m0r, 0.0f), mf1 = fmaxf(m1r, 0.0f);
        const float c0 = __expf(m0r - mf0), c1 = __expf(m1r - mf1);
        const float e0 = __expf(-mf0),      e1f = __expf(-mf1);
        l0r = l0r * c0 + nfar * e0;
        l1r = l1r * c1 + nfar * e1f;
#pragma unroll
        for (int nt = 0; nt < 8; ++nt) {
            o[nt][0] = o[nt][0] * c0 + e0 * fsum[nt].x;
            o[nt][1] = o[nt][1] * c0 + e0 * fsum[nt].y;
            o[nt][2] = o[nt][2] * c1 + e1f * fsum[nt].x;
            o[nt][3] = o[nt][3] * c1 + e1f * fsum[nt].y;
        }
    }

    const float inv0 = 1.0f / l0r, inv1 = 1.0f / l1r;
#pragma unroll
    for (int nt = 0; nt < 8; ++nt) {
        const int d = nt * 8 + lane4 * 2;
        const float v00 = o[nt][0] * inv0, v01 = o[nt][1] * inv0;
        const float v10 = o[nt][2] * inv1, v11 = o[nt][3] * inv1;
        *(float2*)(ctx + r0b + d) = make_float2(v00, v01);
        *(float2*)(ctx + r1b + d) = make_float2(v10, v11);
        *(__half2*)(ctxf + r0b + d) = __floats2half2_rn(v00, v01);
        *(__half2*)(ctxf + r1b + d) = __floats2half2_rn(v10, v11);
    }
}

// ---------------------------------------------------------------------------
extern "C" void kernel_launch(void* const* d_in, const int* in_sizes, int n_in,
                              void* d_out, int out_size)
{
    const float* x   = (const float*)d_in[0];
    const float* spk = (const float*)d_in[1];
    const float* mp  = (const float*)d_in[2];
    const float* Wq  = (const float*)d_in[3];
    const float* bq  = (const float*)d_in[4];
    const float* Wk  = (const float*)d_in[5];
    const float* bk  = (const float*)d_in[6];
    const float* Wv  = (const float*)d_in[7];
    const float* bv  = (const float*)d_in[8];
    const float* Wo  = (const float*)d_in[9];
    const float* bo  = (const float*)d_in[10];
    const float* tau = (const float*)d_in[11];
    const float* Wg  = (const float*)d_in[12];
    const float* bg  = (const float*)d_in[13];
    float* out = (float*)d_out;

    __half *xh16, *xl16, *Wqf, *Wkf, *Wvf;
    __nv_bfloat16 *qh, *ql, *kh, *kl;
    __half *spkf, *vf, *mpf, *ctxf, *cgf, *Wgf, *Wof;
    float *ctx, *vsum;
    cudaGetSymbolAddress((void**)&xh16, g_xh16); cudaGetSymbolAddress((void**)&xl16, g_xl16);
    cudaGetSymbolAddress((void**)&qh,   g_qh);   cudaGetSymbolAddress((void**)&ql,   g_ql);
    cudaGetSymbolAddress((void**)&kh,   g_kh);   cudaGetSymbolAddress((void**)&kl,   g_kl);
    cudaGetSymbolAddress((void**)&Wqf,  g_Wqf);
    cudaGetSymbolAddress((void**)&Wkf,  g_Wkf);
    cudaGetSymbolAddress((void**)&Wvf,  g_Wvf);
    cudaGetSymbolAddress((void**)&spkf, g_spkf); cudaGetSymbolAddress((void**)&vf,   g_vf);
    cudaGetSymbolAddress((void**)&mpf,  g_mpf);  cudaGetSymbolAddress((void**)&ctxf, g_ctxf);
    cudaGetSymbolAddress((void**)&cgf,  g_cgf);
    cudaGetSymbolAddress((void**)&Wgf,  g_Wgf);  cudaGetSymbolAddress((void**)&Wof,  g_Wof);
    cudaGetSymbolAddress((void**)&ctx,  g_ctx);
    cudaGetSymbolAddress((void**)&vsum, g_vsum);

    cudaFuncSetAttribute(gemm_qkv_fused, cudaFuncAttributeMaxDynamicSharedMemorySize, GEMMQ_SMEM);
    cudaFuncSetAttribute(gemm_h<0>,  cudaFuncAttributeMaxDynamicSharedMemorySize, GEMMH_SMEM);
    cudaFuncSetAttribute(gemm_h<2>,  cudaFuncAttributeMaxDynamicSharedMemorySize, GEMMH_SMEM);
    cudaFuncSetAttribute(attn_mma,   cudaFuncAttributeMaxDynamicSharedMemorySize, ATTN_SMEM);

    // ---- one fused prep launch ----
    prep_all<<<(N4TOT + 255) / 256, 256>>>(x, spk, mp, Wq, Wk, Wv, Wo, Wg,
                                           xh16, xl16, spkf, mpf,
                                           Wqf, Wkf, Wvf, Wof, Wgf);

    dim3 tb(256);

    // ---- fused QKV projections: one launch, z = {Q, K, V} ----
    dim3 gq(HIDDEN / 128, MTOT / 128, 3);   // (8, 32, 3)
    gemm_qkv_fused<<<gq, tb, GEMMQ_SMEM>>>(xh16, xl16, Wqf, Wkf, Wvf,
                                           bq, bk, bv, mp,
                                           qh, ql, kh, kl, vf);

    dim3 gv(16, NHEADS, BB);
    vsum_kernel<<<gv, 64>>>(vf, vsum);

    dim3 ga(SSEQ / 128, NHEADS, BB);        // (8,16,4)
    attn_mma<<<ga, tb, ATTN_SMEM>>>(qh, ql, kh, kl, vf, spkf,
                                    tau, vsum, ctx, ctxf);

    dim3 gb(HIDDEN / 128, MTOT / 128);      // (8, 32)
    // gate: cg = ctx * sigmoid([ctx, mp] @ Wg^T + bg)
    gemm_h<2><<<gb, tb, GEMMH_SMEM>>>(ctxf, mpf, HIDDEN, 2 * HIDDEN,
                                      Wgf, bg, ctx, nullptr, cgf, MTOT, HIDDEN);
    // out = cg @ Wo^T + bo
    gemm_h<0><<<gb, tb, GEMMH_SMEM>>>(cgf, nullptr, HIDDEN, HIDDEN,
                                      Wof, bo, nullptr, out, nullptr, MTOT, HIDDEN);
}

// round 16
// speedup vs baseline: 1.0458x; 1.0458x over previous
#include <cuda_runtime.h>
#include <cuda_bf16.h>
#include <cuda_fp16.h>
#include <math.h>
#include <stdint.h>

#define HIDDEN 1024
#define NHEADS 16
#define HDIM   64
#define BB     4
#define SSEQ   1024
#define MTOT   (BB*SSEQ)   // 4096

// ---------------- persistent buffers (device globals) -----------------------
#define BIG (MTOT*HIDDEN)
__device__ __align__(16) __half g_xh16[BIG], g_xl16[BIG];
__device__ __align__(16) __nv_bfloat16 g_qh[BIG],  g_ql[BIG];
__device__ __align__(16) __nv_bfloat16 g_kh[BIG],  g_kl[BIG];
__device__ __align__(16) __half g_Wqf[HIDDEN*HIDDEN];
__device__ __align__(16) __half g_Wkf[HIDDEN*HIDDEN];
__device__ __align__(16) __half g_Wvf[HIDDEN*HIDDEN];
__device__ __align__(16) __half g_spkf[BIG];
__device__ __align__(16) __half g_vf[BIG];
__device__ __align__(16) __half g_mpf[BIG];
__device__ __align__(16) __half g_ctxf[BIG];
__device__ __align__(16) __half g_cgf[BIG];
__device__ __align__(16) __half g_Wgf[2*HIDDEN*HIDDEN];
__device__ __align__(16) __half g_Wof[HIDDEN*HIDDEN];
__device__ float g_ctx[BIG];
__device__ __align__(16) float g_vsum[BB*NHEADS*16*HDIM];

__device__ __forceinline__ float sigmoidf_(float x) {
    return 1.0f / (1.0f + __expf(-x));
}
__device__ __forceinline__ uint32_t smem_to_u32(const void* p) {
    uint32_t a;
    asm("{ .reg .u64 t; cvta.to.shared.u64 t, %1; cvt.u32.u64 %0, t; }"
        : "=r"(a) : "l"(p));
    return a;
}

// ---------------- async copy helpers ----------------------------------------
__device__ __forceinline__ void cp16(uint32_t dst, const void* src) {
    asm volatile("cp.async.cg.shared.global [%0], [%1], 16;" :: "r"(dst), "l"(src));
}
__device__ __forceinline__ void cp_commit() {
    asm volatile("cp.async.commit_group;" ::: "memory");
}
template<int N> __device__ __forceinline__ void cp_wait() {
    asm volatile("cp.async.wait_group %0;" :: "n"(N) : "memory");
}

// ---------------- mma.sync helpers ------------------------------------------
__device__ __forceinline__ void ldsm_x4(uint32_t (&r)[4], uint32_t addr) {
    asm volatile("ldmatrix.sync.aligned.m8n8.x4.shared.b16 {%0,%1,%2,%3}, [%4];"
        : "=r"(r[0]), "=r"(r[1]), "=r"(r[2]), "=r"(r[3]) : "r"(addr));
}
__device__ __forceinline__ void ldsm_x4_trans(uint32_t (&r)[4], uint32_t addr) {
    asm volatile("ldmatrix.sync.aligned.m8n8.x4.trans.shared.b16 {%0,%1,%2,%3}, [%4];"
        : "=r"(r[0]), "=r"(r[1]), "=r"(r[2]), "=r"(r[3]) : "r"(addr));
}
__device__ __forceinline__ void mma_bf16(float (&d)[4], const uint32_t (&a)[4],
                                         const uint32_t* b) {
    asm volatile("mma.sync.aligned.m16n8k16.row.col.f32.bf16.bf16.f32 "
        "{%0,%1,%2,%3}, {%4,%5,%6,%7}, {%8,%9}, {%0,%1,%2,%3};"
        : "+f"(d[0]), "+f"(d[1]), "+f"(d[2]), "+f"(d[3])
        : "r"(a[0]), "r"(a[1]), "r"(a[2]), "r"(a[3]), "r"(b[0]), "r"(b[1]));
}
__device__ __forceinline__ void mma_f16(float (&d)[4], const uint32_t (&a)[4],
                                        const uint32_t* b) {
    asm volatile("mma.sync.aligned.m16n8k16.row.col.f32.f16.f16.f32 "
        "{%0,%1,%2,%3}, {%4,%5,%6,%7}, {%8,%9}, {%0,%1,%2,%3};"
        : "+f"(d[0]), "+f"(d[1]), "+f"(d[2]), "+f"(d[3])
        : "r"(a[0]), "r"(a[1]), "r"(a[2]), "r"(a[3]), "r"(b[0]), "r"(b[1]));
}
__device__ __forceinline__ uint32_t mul_bf16x2(uint32_t a, uint32_t b) {
    uint32_t d;
    asm("mul.rn.bf16x2 %0, %1, %2;" : "=r"(d) : "r"(a), "r"(b));
    return d;
}
__device__ __forceinline__ uint32_t mul_f16x2(uint32_t a, uint32_t b) {
    uint32_t d;
    asm("mul.rn.f16x2 %0, %1, %2;" : "=r"(d) : "r"(a), "r"(b));
    return d;
}
__device__ __forceinline__ void split2pack(float x, float y, uint32_t& hi, uint32_t& lo) {
    __nv_bfloat16 hx = __float2bfloat16_rn(x);
    __nv_bfloat16 hy = __float2bfloat16_rn(y);
    __nv_bfloat16 lx = __float2bfloat16_rn(x - __bfloat162float(hx));
    __nv_bfloat16 ly = __float2bfloat16_rn(y - __bfloat162float(hy));
    hi = (uint32_t)__bfloat16_as_ushort(hx) | ((uint32_t)__bfloat16_as_ushort(hy) << 16);
    lo = (uint32_t)__bfloat16_as_ushort(lx) | ((uint32_t)__bfloat16_as_ushort(ly) << 16);
}
__device__ __forceinline__ void split2pack_f16(float x, float y, uint32_t& hi, uint32_t& lo) {
    __half hx = __float2half_rn(x);
    __half hy = __float2half_rn(y);
    __half lx = __float2half_rn(x - __half2float(hx));
    __half ly = __float2half_rn(y - __half2float(hy));
    hi = (uint32_t)__half_as_ushort(hx) | ((uint32_t)__half_as_ushort(hy) << 16);
    lo = (uint32_t)__half_as_ushort(lx) | ((uint32_t)__half_as_ushort(ly) << 16);
}
__device__ __forceinline__ uint32_t packh2(float x, float y) {
    __half2 h = __floats2half2_rn(x, y);
    return *(uint32_t*)&h;
}

// ---------------- fused prep: all converts in ONE launch ---------------------
#define N4X (BIG/4)
#define N4W (HIDDEN*HIDDEN/4)
#define N4G (2*HIDDEN*HIDDEN/4)
#define N4TOT (3*N4X + 4*N4W + N4G)

__device__ __forceinline__ void cvt4(const float* src, __half* dst, int i) {
    float4 v = ((const float4*)src)[i];
    ((__half2*)dst)[i*2]     = __floats2half2_rn(v.x, v.y);
    ((__half2*)dst)[i*2 + 1] = __floats2half2_rn(v.z, v.w);
}

__global__ __launch_bounds__(256) void prep_all(
    const float* __restrict__ x,  const float* __restrict__ spk,
    const float* __restrict__ mp, const float* __restrict__ Wq,
    const float* __restrict__ Wk, const float* __restrict__ Wv,
    const float* __restrict__ Wo, const float* __restrict__ Wg,
    __half* __restrict__ xh,  __half* __restrict__ xl,
    __half* __restrict__ spkf, __half* __restrict__ mpf,
    __half* __restrict__ Wqf, __half* __restrict__ Wkf,
    __half* __restrict__ Wvf, __half* __restrict__ Wof,
    __half* __restrict__ Wgf)
{
    int i = blockIdx.x * blockDim.x + threadIdx.x;
    if (i >= N4TOT) return;
    if (i < N4X) {
        float4 v = ((const float4*)x)[i];
        uint2 hi, lo;
        split2pack_f16(v.x, v.y, hi.x, lo.x);
        split2pack_f16(v.z, v.w, hi.y, lo.y);
        ((uint2*)xh)[i] = hi;
        ((uint2*)xl)[i] = lo;
        return;
    }
    i -= N4X;
    if (i < N4X) { cvt4(spk, spkf, i); return; }
    i -= N4X;
    if (i < N4X) { cvt4(mp, mpf, i); return; }
    i -= N4X;
    if (i < N4W) { cvt4(Wq, Wqf, i); return; }
    i -= N4W;
    if (i < N4W) { cvt4(Wk, Wkf, i); return; }
    i -= N4W;
    if (i < N4W) { cvt4(Wv, Wvf, i); return; }
    i -= N4W;
    if (i < N4W) { cvt4(Wo, Wof, i); return; }
    i -= N4W;
    cvt4(Wg, Wgf, i);
}

// ---------------- per-(b,h,ktile) gated-V column sums (fp16 V) ---------------
__global__ __launch_bounds__(64) void vsum_kernel(
    const __half* __restrict__ vf_g, float* __restrict__ vsum)
{
    const int d = threadIdx.x;
    const int t = blockIdx.x, h = blockIdx.y, b = blockIdx.z;
    const size_t base = ((size_t)(b * SSEQ + t * 64)) * HIDDEN + h * HDIM + d;
    float s = 0.0f;
#pragma unroll 8
    for (int r = 0; r < 64; ++r)
        s += __half2float(vf_g[base + (size_t)r * HIDDEN]);
    vsum[(((size_t)b * NHEADS + h) * 16 + t) * HDIM + d] = s;
}

// ---------------------------------------------------------------------------
// Fused QKV projection GEMM: ONE launch, gridDim.z = 3 (0:Q, 1:K, 2:V).
// Q/K: fp16 2-term.  V: fp16 1-term.  3-stage cp.async, 2 CTAs/SM.
// ---------------------------------------------------------------------------
#define BKP      40
#define ARR_B    (128*BKP*2)          // 10240
#define STAGE_Q  (3*ARR_B)            // 30720
#define GEMMQ_SMEM (3*STAGE_Q)        // 92160

__global__ __launch_bounds__(256, 2) void gemm_qkv_fused(
    const __half* __restrict__ Ah_g, const __half* __restrict__ Al_g,
    const __half* __restrict__ WqB, const __half* __restrict__ WkB,
    const __half* __restrict__ WvB,
    const float* __restrict__ bq, const float* __restrict__ bk,
    const float* __restrict__ bv, const float* __restrict__ mpE,
    __nv_bfloat16* __restrict__ qh_o, __nv_bfloat16* __restrict__ ql_o,
    __nv_bfloat16* __restrict__ kh_o, __nv_bfloat16* __restrict__ kl_o,
    __half* __restrict__ vf_o)
{
    extern __shared__ __align__(128) char smem[];
    const uint32_t sbase = smem_to_u32(smem);
    const int tid = threadIdx.x, wid = tid >> 5, lane = tid & 31;
    const int m0 = blockIdx.y * 128, n0 = blockIdx.x * 128;
    const int z = blockIdx.z;
    const int K = HIDDEN, N = HIDDEN;
    const int NCH = K >> 5;

    const __half* Bm   = (z == 0) ? WqB : (z == 1) ? WkB : WvB;
    const float*  bias = (z == 0) ? bq  : (z == 1) ? bk  : bv;
    const bool two_term = (z != 2);

    const int wm = (wid >> 1) * 32;
    const int wn = (wid & 1) * 64;

    float acc[2][8][4];
#pragma unroll
    for (int mt = 0; mt < 2; mt++)
#pragma unroll
        for (int nt = 0; nt < 8; nt++)
#pragma unroll
            for (int j = 0; j < 4; j++) acc[mt][nt][j] = 0.0f;

    auto fill = [&](int c) {
        const uint32_t st = sbase + (uint32_t)(c % 3) * STAGE_Q;
        const int k0 = c * 32;
#pragma unroll
        for (int i = 0; i < 2; ++i) {
            const int s = tid + i * 256;
            const int row = s >> 2, q = s & 3;
            const uint32_t d = st + (uint32_t)(row * 80 + q * 16);
            const size_t ga = ((size_t)(m0 + row) * K + k0 + q * 8) * 2;
            cp16(d,           (const char*)Ah_g + ga);
            if (two_term) cp16(d + ARR_B, (const char*)Al_g + ga);
            const size_t gb = ((size_t)(n0 + row) * K + k0 + q * 8) * 2;
            cp16(d + 2*ARR_B, (const char*)Bm + gb);
        }
        cp_commit();
    };

    const uint32_t a_lane_off = (uint32_t)((lane & 15) * (BKP * 2) + (lane >> 4) * 16);
    const uint32_t b_lane_off = (uint32_t)(((lane & 7) + ((lane >> 4) << 3)) * (BKP * 2)
                                           + ((lane >> 3) & 1) * 16);

    auto compute_chunk = [&](int c) {
        const uint32_t b = sbase + (uint32_t)(c % 3) * STAGE_Q;
#pragma unroll
        for (int ks = 0; ks < 2; ++ks) {
            const uint32_t koffb = (uint32_t)(ks * 32);
            uint32_t ah[2][4], al[2][4];
#pragma unroll
            for (int mt = 0; mt < 2; ++mt) {
                const uint32_t off = (uint32_t)((wm + mt * 16) * (BKP * 2)) + a_lane_off + koffb;
                ldsm_x4(ah[mt], b + off);
                if (two_term) ldsm_x4(al[mt], b + ARR_B + off);
            }
            uint32_t bh[8][2];
#pragma unroll
            for (int np = 0; np < 4; ++np) {
                const uint32_t off = (uint32_t)((wn + np * 16) * (BKP * 2)) + b_lane_off + koffb;
                uint32_t r4[4];
                ldsm_x4(r4, b + 2*ARR_B + off);
                bh[np*2][0] = r4[0]; bh[np*2][1] = r4[1];
                bh[np*2+1][0] = r4[2]; bh[np*2+1][1] = r4[3];
            }
#pragma unroll
            for (int mt = 0; mt < 2; ++mt)
#pragma unroll
                for (int nt = 0; nt < 8; ++nt) {
                    mma_f16(acc[mt][nt], ah[mt], bh[nt]);
                    if (two_term) mma_f16(acc[mt][nt], al[mt], bh[nt]);
                }
        }
    };

    fill(0);
    fill(1);
    for (int c = 0; c < NCH; ++c) {
        if (c < NCH - 1) cp_wait<1>(); else cp_wait<0>();
        __syncthreads();
        if (c + 2 < NCH) fill(c + 2);
        compute_chunk(c);
    }

    __nv_bfloat16* Ch = (z == 0) ? qh_o : kh_o;
    __nv_bfloat16* Cl = (z == 0) ? ql_o : kl_o;

#pragma unroll
    for (int mt = 0; mt < 2; ++mt) {
        const int m = m0 + wm + mt * 16 + (lane >> 2);
#pragma unroll
        for (int nt = 0; nt < 8; ++nt) {
            const int n = n0 + wn + nt * 8 + (lane & 3) * 2;
            const float2 bv2 = *(const float2*)(bias + n);
#pragma unroll
            for (int half = 0; half < 2; ++half) {
                const size_t off = (size_t)(m + half * 8) * N + n;
                float v0 = acc[mt][nt][half*2 + 0] + bv2.x;
                float v1 = acc[mt][nt][half*2 + 1] + bv2.y;
                if (z == 2) {
                    float2 e = *(const float2*)(mpE + off);
                    v0 *= sigmoidf_(e.x); v1 *= sigmoidf_(e.y);
                    *(uint32_t*)((char*)vf_o + off * 2) = packh2(v0, v1);
                } else {
                    uint32_t hi, lo;
                    split2pack(v0, v1, hi, lo);
                    *(uint32_t*)((char*)Ch + off * 2) = hi;
                    *(uint32_t*)((char*)Cl + off * 2) = lo;
                }
            }
        }
    }
}

// ---------------------------------------------------------------------------
// Single-pass fp16 NT GEMM (gate + output), 3-stage, 2 CTAs/SM.
// ---------------------------------------------------------------------------
#define STAGE_H  (2*ARR_B)            // 20480
#define GEMMH_SMEM (3*STAGE_H)        // 61440

template<int EPI>
__global__ __launch_bounds__(256, 2) void gemm_h(
    const __half* __restrict__ A1, const __half* __restrict__ A2,
    int K1, int K,
    const __half* __restrict__ Bm,
    const float* __restrict__ bias, const float* __restrict__ E,
    float* __restrict__ C, __half* __restrict__ Cf,
    int M, int N)
{
    extern __shared__ __align__(128) char smem[];
    const uint32_t sbase = smem_to_u32(smem);
    const int tid = threadIdx.x, wid = tid >> 5, lane = tid & 31;
    const int m0 = blockIdx.y * 128, n0 = blockIdx.x * 128;
    const int NCH = K >> 5;

    const int wm = (wid >> 1) * 32;
    const int wn = (wid & 1) * 64;

    float acc[2][8][4];
#pragma unroll
    for (int mt = 0; mt < 2; mt++)
#pragma unroll
        for (int nt = 0; nt < 8; nt++)
#pragma unroll
            for (int j = 0; j < 4; j++) acc[mt][nt][j] = 0.0f;

    auto fill = [&](int c) {
        const uint32_t st = sbase + (uint32_t)(c % 3) * STAGE_H;
        const int k0 = c * 32;
        const __half* Ap; int lda, koff;
        if (k0 < K1) { Ap = A1; lda = K1;     koff = k0; }
        else         { Ap = A2; lda = K - K1; koff = k0 - K1; }
#pragma unroll
        for (int i = 0; i < 2; ++i) {
            const int s = tid + i * 256;
            const int row = s >> 2, q = s & 3;
            const uint32_t d = st + (uint32_t)(row * 80 + q * 16);
            const size_t ga = ((size_t)(m0 + row) * lda + koff + q * 8) * 2;
            cp16(d,           (const char*)Ap + ga);
            const size_t gb = ((size_t)(n0 + row) * K + k0 + q * 8) * 2;
            cp16(d + ARR_B,   (const char*)Bm + gb);
        }
        cp_commit();
    };

    const uint32_t a_lane_off = (uint32_t)((lane & 15) * (BKP * 2) + (lane >> 4) * 16);
    const uint32_t b_lane_off = (uint32_t)(((lane & 7) + ((lane >> 4) << 3)) * (BKP * 2)
                                           + ((lane >> 3) & 1) * 16);

    auto compute_chunk = [&](int c) {
        const uint32_t b = sbase + (uint32_t)(c % 3) * STAGE_H;
#pragma unroll
        for (int ks = 0; ks < 2; ++ks) {
            const uint32_t koffb = (uint32_t)(ks * 32);
            uint32_t ah[2][4];
#pragma unroll
            for (int mt = 0; mt < 2; ++mt) {
                const uint32_t off = (uint32_t)((wm + mt * 16) * (BKP * 2)) + a_lane_off + koffb;
                ldsm_x4(ah[mt], b + off);
            }
            uint32_t bh[8][2];
#pragma unroll
            for (int np = 0; np < 4; ++np) {
                const uint32_t off = (uint32_t)((wn + np * 16) * (BKP * 2)) + b_lane_off + koffb;
                uint32_t r4[4];
                ldsm_x4(r4, b + ARR_B + off);
                bh[np*2][0] = r4[0]; bh[np*2][1] = r4[1];
                bh[np*2+1][0] = r4[2]; bh[np*2+1][1] = r4[3];
            }
#pragma unroll
            for (int mt = 0; mt < 2; ++mt)
#pragma unroll
                for (int nt = 0; nt < 8; ++nt)
                    mma_f16(acc[mt][nt], ah[mt], bh[nt]);
        }
    };

    fill(0);
    fill(1);
    for (int c = 0; c < NCH; ++c) {
        if (c < NCH - 1) cp_wait<1>(); else cp_wait<0>();
        __syncthreads();
        if (c + 2 < NCH) fill(c + 2);
        compute_chunk(c);
    }

#pragma unroll
    for (int mt = 0; mt < 2; ++mt) {
        const int m = m0 + wm + mt * 16 + (lane >> 2);
#pragma unroll
        for (int nt = 0; nt < 8; ++nt) {
            const int n = n0 + wn + nt * 8 + (lane & 3) * 2;
            const float2 bv = *(const float2*)(bias + n);
#pragma unroll
            for (int half = 0; half < 2; ++half) {
                const size_t off = (size_t)(m + half * 8) * N + n;
                float v0 = acc[mt][nt][half*2 + 0] + bv.x;
                float v1 = acc[mt][nt][half*2 + 1] + bv.y;
                if (EPI == 2) {
                    float2 e = *(const float2*)(E + off);
                    v0 = e.x * sigmoidf_(v0); v1 = e.y * sigmoidf_(v1);
                    *(__half2*)(Cf + off) = __floats2half2_rn(v0, v1);
                } else {
                    *(float2*)(C + off) = make_float2(v0, v1);
                }
            }
        }
    }
}

// ---------------------------------------------------------------------------
// Tensor-core flash attention, decay-window tile skipping (dt<96).
// 128-thread CTAs (4 warps), q-tile 64 rows, 2-stage pipeline, 2 CTAs/SM.
// Mask exps via geometric recurrence (4 expf seeds/tile).
// ---------------------------------------------------------------------------
#define KROW    144
#define ARR_A   (64*KROW)              // 9216
#define STAGE_A (4*ARR_A)              // 36864
#define ATTN_SMEM (2*STAGE_A)          // 73728 -> 2 CTAs/SM
#define SCALE2  0x3E003E00u            // bf16x2 {0.125, 0.125}
#define HSCALE2 0x30003000u            // f16x2  {0.125, 0.125}

__global__ __launch_bounds__(128, 2) void attn_mma(
    const __nv_bfloat16* __restrict__ qh_g, const __nv_bfloat16* __restrict__ ql_g,
    const __nv_bfloat16* __restrict__ kh_g, const __nv_bfloat16* __restrict__ kl_g,
    const __half* __restrict__ vf_g, const __half* __restrict__ skf_g,
    const float* __restrict__ tau, const float* __restrict__ vsum,
    float* __restrict__ ctx, __half* __restrict__ ctxf)
{
    extern __shared__ __align__(128) char smem[];
    const uint32_t sb = smem_to_u32(smem);
    const int tid = threadIdx.x, wid = tid >> 5, lane = tid & 31;
    const int lane4 = lane & 3, laneq = lane >> 2;
    const int h = blockIdx.y, b = blockIdx.z;
    const int q0 = blockIdx.x * 64;
    const float inv_tau = 1.0f / tau[h];
    const float r8  = __expf(8.0f * inv_tau);
    const float r8i = __expf(-8.0f * inv_tau);
    const float e1  = __expf(inv_tau);
    const float e1i = __expf(-inv_tau);

    // near window for 64-row q tile: tile near iff k0 >= q0-158 && k0 <= q0+158
    const int lo = q0 - 158;
    const int ktmin = lo <= 0 ? 0 : ((lo + 63) >> 6);
    const int ktmax_ = (q0 + 158) >> 6;
    const int ktmax = ktmax_ > 15 ? 15 : ktmax_;

    const int ti0 = q0 + wid * 16 + laneq;
    const int ti1 = ti0 + 8;
    const size_t r0b = (size_t)(b * SSEQ + ti0) * HIDDEN + h * HDIM;
    const size_t r1b = (size_t)(b * SSEQ + ti1) * HIDDEN + h * HDIM;

    uint32_t qh[4][4], ql[4][4], sqf[4][4];
    {
        const char* qhp = (const char*)qh_g;
        const char* qlp = (const char*)ql_g;
        const char* sfp = (const char*)skf_g;
#pragma unroll
        for (int ks = 0; ks < 4; ++ks) {
            const int kc = ks * 16 + lane4 * 2;
            const size_t o00 = (r0b + kc) * 2, o10 = (r1b + kc) * 2;
            const size_t o01 = o00 + 16,       o11 = o10 + 16;
            qh[ks][0] = mul_bf16x2(*(const uint32_t*)(qhp + o00), SCALE2);
            qh[ks][1] = mul_bf16x2(*(const uint32_t*)(qhp + o10), SCALE2);
            qh[ks][2] = mul_bf16x2(*(const uint32_t*)(qhp + o01), SCALE2);
            qh[ks][3] = mul_bf16x2(*(const uint32_t*)(qhp + o11), SCALE2);
            ql[ks][0] = mul_bf16x2(*(const uint32_t*)(qlp + o00), SCALE2);
            ql[ks][1] = mul_bf16x2(*(const uint32_t*)(qlp + o10), SCALE2);
            ql[ks][2] = mul_bf16x2(*(const uint32_t*)(qlp + o01), SCALE2);
            ql[ks][3] = mul_bf16x2(*(const uint32_t*)(qlp + o11), SCALE2);
            sqf[ks][0] = mul_f16x2(*(const uint32_t*)(sfp + o00), HSCALE2);
            sqf[ks][1] = mul_f16x2(*(const uint32_t*)(sfp + o10), HSCALE2);
            sqf[ks][2] = mul_f16x2(*(const uint32_t*)(sfp + o01), HSCALE2);
            sqf[ks][3] = mul_f16x2(*(const uint32_t*)(sfp + o11), HSCALE2);
        }
    }

    float m0r = -1e30f, m1r = -1e30f, l0r = 0.0f, l1r = 0.0f;
    float o[8][4];
#pragma unroll
    for (int nt = 0; nt < 8; nt++)
#pragma unroll
        for (int j = 0; j < 4; j++) o[nt][j] = 0.0f;

    auto fill_tile = [&](int kt) {
        const uint32_t st = sb + (uint32_t)(kt & 1) * STAGE_A;
        const size_t base = ((size_t)(b * SSEQ + kt * 64)) * HIDDEN + h * HDIM;
#pragma unroll
        for (int i = 0; i < 4; ++i) {
            const int s = tid + i * 128;
            const int row = s >> 3, q = s & 7;
            const size_t g2 = (base + (size_t)row * HIDDEN + q * 8) * 2;
            const uint32_t d = st + (uint32_t)(row * KROW + q * 16);
            cp16(d + 0*ARR_A, (const char*)kh_g  + g2);
            cp16(d + 1*ARR_A, (const char*)kl_g  + g2);
            cp16(d + 2*ARR_A, (const char*)skf_g + g2);
            cp16(d + 3*ARR_A, (const char*)vf_g  + g2);
        }
        cp_commit();
    };

    const uint32_t b_off = (uint32_t)(((lane & 7) + ((lane >> 4) << 3)) * KROW
                                      + ((lane >> 3) & 1) * 16);
    const uint32_t v_off = (uint32_t)(((lane & 7) + ((lane >> 3) & 1) * 8) * KROW
                                      + ((lane >> 4) & 1) * 16);
    const float ti0f = (float)ti0, ti1f = (float)ti1;

    fill_tile(ktmin);
    if (ktmin + 1 <= ktmax) fill_tile(ktmin + 1);
    for (int kt = ktmin; kt <= ktmax; ++kt) {
        if (kt < ktmax) cp_wait<1>(); else cp_wait<0>();
        __syncthreads();

        const uint32_t st = sb + (uint32_t)(kt & 1) * STAGE_A;
        const int k0 = kt * 64;

        float s[8][4], sp[8][4];
#pragma unroll
        for (int nt = 0; nt < 8; nt++)
#pragma unroll
            for (int j = 0; j < 4; j++) { s[nt][j] = 0.0f; sp[nt][j] = 0.0f; }

#pragma unroll
        for (int ks = 0; ks < 4; ++ks) {
            const uint32_t kb = (uint32_t)(ks * 32);
#pragma unroll
            for (int n8 = 0; n8 < 4; ++n8) {
                const uint32_t off = (uint32_t)(n8 * 16 * KROW) + b_off + kb;
                uint32_t rh[4], rl[4];
                ldsm_x4(rh, st + 0*ARR_A + off);
                ldsm_x4(rl, st + 1*ARR_A + off);
                mma_bf16(s[2*n8],   qh[ks], &rh[0]);
                mma_bf16(s[2*n8],   qh[ks], &rl[0]);
                mma_bf16(s[2*n8],   ql[ks], &rh[0]);
                mma_bf16(s[2*n8+1], qh[ks], &rh[2]);
                mma_bf16(s[2*n8+1], qh[ks], &rl[2]);
                mma_bf16(s[2*n8+1], ql[ks], &rh[2]);
                uint32_t rs[4];
                ldsm_x4(rs, st + 2*ARR_A + off);
                mma_f16(sp[2*n8],   sqf[ks], &rs[0]);
                mma_f16(sp[2*n8+1], sqf[ks], &rs[2]);
            }
        }

        // ---- mask via geometric recurrence + online softmax ----
        {
            const float d00 = (float)(k0 + lane4 * 2) - ti0f;
            const float d10 = (float)(k0 + lane4 * 2) - ti1f;
            float u0 = __expf(d00 * inv_tau), v0 = __expf(-d00 * inv_tau);
            float u1 = __expf(d10 * inv_tau), v1 = __expf(-d10 * inv_tau);
            float u0b = u0 * e1, v0b = v0 * e1i;
            float u1b = u1 * e1, v1b = v1 * e1i;
            float rmax0 = -1e30f, rmax1 = -1e30f;
#pragma unroll
            for (int nt = 0; nt < 8; ++nt) {
                const float e00 = fminf(u0, v0);
                const float e01 = fminf(u0b, v0b);
                const float e10 = fminf(u1, v1);
                const float e11 = fminf(u1b, v1b);
                u0 *= r8; v0 *= r8i; u0b *= r8; v0b *= r8i;
                u1 *= r8; v1 *= r8i; u1b *= r8; v1b *= r8i;
                s[nt][0] = s[nt][0] * e00 * (1.0f + sp[nt][0]);
                s[nt][1] = s[nt][1] * e01 * (1.0f + sp[nt][1]);
                s[nt][2] = s[nt][2] * e10 * (1.0f + sp[nt][2]);
                s[nt][3] = s[nt][3] * e11 * (1.0f + sp[nt][3]);
                rmax0 = fmaxf(rmax0, fmaxf(s[nt][0], s[nt][1]));
                rmax1 = fmaxf(rmax1, fmaxf(s[nt][2], s[nt][3]));
            }
            rmax0 = fmaxf(rmax0, __shfl_xor_sync(0xffffffffu, rmax0, 1));
            rmax0 = fmaxf(rmax0, __shfl_xor_sync(0xffffffffu, rmax0, 2));
            rmax1 = fmaxf(rmax1, __shfl_xor_sync(0xffffffffu, rmax1, 1));
            rmax1 = fmaxf(rmax1, __shfl_xor_sync(0xffffffffu, rmax1, 2));
            const float mn0 = fmaxf(m0r, rmax0), mn1 = fmaxf(m1r, rmax1);
            const float c0 = __expf(m0r - mn0), c1 = __expf(m1r - mn1);
            float ls0 = 0.0f, ls1 = 0.0f;
#pragma unroll
            for (int nt = 0; nt < 8; ++nt) {
                float p;
                p = __expf(s[nt][0] - mn0); s[nt][0] = p; ls0 += p;
                p = __expf(s[nt][1] - mn0); s[nt][1] = p; ls0 += p;
                p = __expf(s[nt][2] - mn1); s[nt][2] = p; ls1 += p;
                p = __expf(s[nt][3] - mn1); s[nt][3] = p; ls1 += p;
            }
            ls0 += __shfl_xor_sync(0xffffffffu, ls0, 1);
            ls0 += __shfl_xor_sync(0xffffffffu, ls0, 2);
            ls1 += __shfl_xor_sync(0xffffffffu, ls1, 1);
            ls1 += __shfl_xor_sync(0xffffffffu, ls1, 2);
            l0r = l0r * c0 + ls0;  m0r = mn0;
            l1r = l1r * c1 + ls1;  m1r = mn1;
#pragma unroll
            for (int nt = 0; nt < 8; ++nt) {
                o[nt][0] *= c0; o[nt][1] *= c0;
                o[nt][2] *= c1; o[nt][3] *= c1;
            }
        }

#pragma unroll
        for (int ks = 0; ks < 4; ++ks) {
            uint32_t ph[4];
            ph[0] = packh2(s[2*ks][0],   s[2*ks][1]);
            ph[1] = packh2(s[2*ks][2],   s[2*ks][3]);
            ph[2] = packh2(s[2*ks+1][0], s[2*ks+1][1]);
            ph[3] = packh2(s[2*ks+1][2], s[2*ks+1][3]);
            const uint32_t roff = (uint32_t)(ks * 16 * KROW) + v_off;
#pragma unroll
            for (int n8 = 0; n8 < 4; ++n8) {
                uint32_t vfr[4];
                ldsm_x4_trans(vfr, st + 3*ARR_A + roff + (uint32_t)(n8 * 32));
                mma_f16(o[2*n8],   ph, &vfr[0]);
                mma_f16(o[2*n8+1], ph, &vfr[2]);
            }
        }

        if (kt + 2 <= ktmax) {
            __syncthreads();
            fill_tile(kt + 2);
        }
    }

    {
        float2 fsum[8];
#pragma unroll
        for (int nt = 0; nt < 8; ++nt) { fsum[nt].x = 0.0f; fsum[nt].y = 0.0f; }
        const float2* vsbase = (const float2*)(vsum + (((size_t)b * NHEADS + h) * 16) * HDIM);
        for (int t = 0; t < 16; ++t) {
            if (t >= ktmin && t <= ktmax) continue;
            const float2* vs = vsbase + t * (HDIM / 2);
#pragma unroll
            for (int nt = 0; nt < 8; ++nt) {
                float2 v = vs[nt * 4 + lane4];
                fsum[nt].x += v.x; fsum[nt].y += v.y;
            }
        }
        const float nfar = (float)(64 * (16 - (ktmax - ktmin + 1)));
        const float mf0 = fmaxf(m0r, 0.0f), mf1 = fmaxf(m1r, 0.0f);
        const float c0 = __expf(m0r - mf0), c1 = __expf(m1r - mf1);
        const float e0 = __expf(-mf0),      e1f = __expf(-mf1);
        l0r = l0r * c0 + nfar * e0;
        l1r = l1r * c1 + nfar * e1f;
#pragma unroll
        for (int nt = 0; nt < 8; ++nt) {
            o[nt][0] = o[nt][0] * c0 + e0 * fsum[nt].x;
            o[nt][1] = o[nt][1] * c0 + e0 * fsum[nt].y;
            o[nt][2] = o[nt][2] * c1 + e1f * fsum[nt].x;
            o[nt][3] = o[nt][3] * c1 + e1f * fsum[nt].y;
        }
    }

    const float inv0 = 1.0f / l0r, inv1 = 1.0f / l1r;
#pragma unroll
    for (int nt = 0; nt < 8; ++nt) {
        const int d = nt * 8 + lane4 * 2;
        const float v00 = o[nt][0] * inv0, v01 = o[nt][1] * inv0;
        const float v10 = o[nt][2] * inv1, v11 = o[nt][3] * inv1;
        *(float2*)(ctx + r0b + d) = make_float2(v00, v01);
        *(float2*)(ctx + r1b + d) = make_float2(v10, v11);
        *(__half2*)(ctxf + r0b + d) = __floats2half2_rn(v00, v01);
        *(__half2*)(ctxf + r1b + d) = __floats2half2_rn(v10, v11);
    }
}

// ---------------------------------------------------------------------------
extern "C" void kernel_launch(void* const* d_in, const int* in_sizes, int n_in,
                              void* d_out, int out_size)
{
    const float* x   = (const float*)d_in[0];
    const float* spk = (const float*)d_in[1];
    const float* mp  = (const float*)d_in[2];
    const float* Wq  = (const float*)d_in[3];
    const float* bq  = (const float*)d_in[4];
    const float* Wk  = (const float*)d_in[5];
    const float* bk  = (const float*)d_in[6];
    const float* Wv  = (const float*)d_in[7];
    const float* bv  = (const float*)d_in[8];
    const float* Wo  = (const float*)d_in[9];
    const float* bo  = (const float*)d_in[10];
    const float* tau = (const float*)d_in[11];
    const float* Wg  = (const float*)d_in[12];
    const float* bg  = (const float*)d_in[13];
    float* out = (float*)d_out;

    __half *xh16, *xl16, *Wqf, *Wkf, *Wvf;
    __nv_bfloat16 *qh, *ql, *kh, *kl;
    __half *spkf, *vf, *mpf, *ctxf, *cgf, *Wgf, *Wof;
    float *ctx, *vsum;
    cudaGetSymbolAddress((void**)&xh16, g_xh16); cudaGetSymbolAddress((void**)&xl16, g_xl16);
    cudaGetSymbolAddress((void**)&qh,   g_qh);   cudaGetSymbolAddress((void**)&ql,   g_ql);
    cudaGetSymbolAddress((void**)&kh,   g_kh);   cudaGetSymbolAddress((void**)&kl,   g_kl);
    cudaGetSymbolAddress((void**)&Wqf,  g_Wqf);
    cudaGetSymbolAddress((void**)&Wkf,  g_Wkf);
    cudaGetSymbolAddress((void**)&Wvf,  g_Wvf);
    cudaGetSymbolAddress((void**)&spkf, g_spkf); cudaGetSymbolAddress((void**)&vf,   g_vf);
    cudaGetSymbolAddress((void**)&mpf,  g_mpf);  cudaGetSymbolAddress((void**)&ctxf, g_ctxf);
    cudaGetSymbolAddress((void**)&cgf,  g_cgf);
    cudaGetSymbolAddress((void**)&Wgf,  g_Wgf);  cudaGetSymbolAddress((void**)&Wof,  g_Wof);
    cudaGetSymbolAddress((void**)&ctx,  g_ctx);
    cudaGetSymbolAddress((void**)&vsum, g_vsum);

    cudaFuncSetAttribute(gemm_qkv_fused, cudaFuncAttributeMaxDynamicSharedMemorySize, GEMMQ_SMEM);
    cudaFuncSetAttribute(gemm_h<0>,  cudaFuncAttributeMaxDynamicSharedMemorySize, GEMMH_SMEM);
    cudaFuncSetAttribute(gemm_h<2>,  cudaFuncAttributeMaxDynamicSharedMemorySize, GEMMH_SMEM);
    cudaFuncSetAttribute(attn_mma,   cudaFuncAttributeMaxDynamicSharedMemorySize, ATTN_SMEM);

    // ---- one fused prep launch ----
    prep_all<<<(N4TOT + 255) / 256, 256>>>(x, spk, mp, Wq, Wk, Wv, Wo, Wg,
                                           xh16, xl16, spkf, mpf,
                                           Wqf, Wkf, Wvf, Wof, Wgf);

    dim3 tb(256);

    // ---- fused QKV projections: one launch, z = {Q, K, V} ----
    dim3 gq(HIDDEN / 128, MTOT / 128, 3);   // (8, 32, 3)
    gemm_qkv_fused<<<gq, tb, GEMMQ_SMEM>>>(xh16, xl16, Wqf, Wkf, Wvf,
                                           bq, bk, bv, mp,
                                           qh, ql, kh, kl, vf);

    dim3 gv(16, NHEADS, BB);
    vsum_kernel<<<gv, 64>>>(vf, vsum);

    // ---- attention: 128-thread CTAs, 64-row q tiles, 2 CTAs/SM ----
    dim3 ga(SSEQ / 64, NHEADS, BB);         // (16,16,4) = 1024
    attn_mma<<<ga, dim3(128), ATTN_SMEM>>>(qh, ql, kh, kl, vf, spkf,
                                           tau, vsum, ctx, ctxf);

    dim3 gb(HIDDEN / 128, MTOT / 128);      // (8, 32)
    // gate: cg = ctx * sigmoid([ctx, mp] @ Wg^T + bg)
    gemm_h<2><<<gb, tb, GEMMH_SMEM>>>(ctxf, mpf, HIDDEN, 2 * HIDDEN,
                                      Wgf, bg, ctx, nullptr, cgf, MTOT, HIDDEN);
    // out = cg @ Wo^T + bo
    gemm_h<0><<<gb, tb, GEMMH_SMEM>>>(cgf, nullptr, HIDDEN, HIDDEN,
                                      Wof, bo, nullptr, out, nullptr, MTOT, HIDDEN);
}

// round 17
// speedup vs baseline: 1.0546x; 1.0084x over previous
#include <cuda_runtime.h>
#include <cuda_bf16.h>
#include <cuda_fp16.h>
#include <math.h>
#include <stdint.h>

#define HIDDEN 1024
#define NHEADS 16
#define HDIM   64
#define BB     4
#define SSEQ   1024
#define MTOT   (BB*SSEQ)   // 4096

// ---------------- persistent buffers (device globals) -----------------------
#define BIG (MTOT*HIDDEN)
__device__ __align__(16) __half g_xh16[BIG], g_xl16[BIG];
__device__ __align__(16) __nv_bfloat16 g_qh[BIG],  g_ql[BIG];
__device__ __align__(16) __nv_bfloat16 g_kh[BIG],  g_kl[BIG];
__device__ __align__(16) __half g_Wqf[HIDDEN*HIDDEN];
__device__ __align__(16) __half g_Wkf[HIDDEN*HIDDEN];
__device__ __align__(16) __half g_Wvf[HIDDEN*HIDDEN];
__device__ __align__(16) __half g_spkf[BIG];
__device__ __align__(16) __half g_vf[BIG];
__device__ __align__(16) __half g_mpf[BIG];
__device__ __align__(16) __half g_ctxf[BIG];
__device__ __align__(16) __half g_cgf[BIG];
__device__ __align__(16) __half g_Wgf[2*HIDDEN*HIDDEN];
__device__ __align__(16) __half g_Wof[HIDDEN*HIDDEN];
__device__ __align__(16) float g_vsum[BB*NHEADS*16*HDIM];

__device__ __forceinline__ float sigmoidf_(float x) {
    return 1.0f / (1.0f + __expf(-x));
}
__device__ __forceinline__ uint32_t smem_to_u32(const void* p) {
    uint32_t a;
    asm("{ .reg .u64 t; cvta.to.shared.u64 t, %1; cvt.u32.u64 %0, t; }"
        : "=r"(a) : "l"(p));
    return a;
}

// ---------------- async copy helpers ----------------------------------------
__device__ __forceinline__ void cp16(uint32_t dst, const void* src) {
    asm volatile("cp.async.cg.shared.global [%0], [%1], 16;" :: "r"(dst), "l"(src));
}
__device__ __forceinline__ void cp_commit() {
    asm volatile("cp.async.commit_group;" ::: "memory");
}
template<int N> __device__ __forceinline__ void cp_wait() {
    asm volatile("cp.async.wait_group %0;" :: "n"(N) : "memory");
}

// ---------------- mma.sync helpers ------------------------------------------
__device__ __forceinline__ void ldsm_x4(uint32_t (&r)[4], uint32_t addr) {
    asm volatile("ldmatrix.sync.aligned.m8n8.x4.shared.b16 {%0,%1,%2,%3}, [%4];"
        : "=r"(r[0]), "=r"(r[1]), "=r"(r[2]), "=r"(r[3]) : "r"(addr));
}
__device__ __forceinline__ void ldsm_x4_trans(uint32_t (&r)[4], uint32_t addr) {
    asm volatile("ldmatrix.sync.aligned.m8n8.x4.trans.shared.b16 {%0,%1,%2,%3}, [%4];"
        : "=r"(r[0]), "=r"(r[1]), "=r"(r[2]), "=r"(r[3]) : "r"(addr));
}
__device__ __forceinline__ void mma_bf16(float (&d)[4], const uint32_t (&a)[4],
                                         const uint32_t* b) {
    asm volatile("mma.sync.aligned.m16n8k16.row.col.f32.bf16.bf16.f32 "
        "{%0,%1,%2,%3}, {%4,%5,%6,%7}, {%8,%9}, {%0,%1,%2,%3};"
        : "+f"(d[0]), "+f"(d[1]), "+f"(d[2]), "+f"(d[3])
        : "r"(a[0]), "r"(a[1]), "r"(a[2]), "r"(a[3]), "r"(b[0]), "r"(b[1]));
}
__device__ __forceinline__ void mma_f16(float (&d)[4], const uint32_t (&a)[4],
                                        const uint32_t* b) {
    asm volatile("mma.sync.aligned.m16n8k16.row.col.f32.f16.f16.f32 "
        "{%0,%1,%2,%3}, {%4,%5,%6,%7}, {%8,%9}, {%0,%1,%2,%3};"
        : "+f"(d[0]), "+f"(d[1]), "+f"(d[2]), "+f"(d[3])
        : "r"(a[0]), "r"(a[1]), "r"(a[2]), "r"(a[3]), "r"(b[0]), "r"(b[1]));
}
__device__ __forceinline__ uint32_t mul_bf16x2(uint32_t a, uint32_t b) {
    uint32_t d;
    asm("mul.rn.bf16x2 %0, %1, %2;" : "=r"(d) : "r"(a), "r"(b));
    return d;
}
__device__ __forceinline__ uint32_t mul_f16x2(uint32_t a, uint32_t b) {
    uint32_t d;
    asm("mul.rn.f16x2 %0, %1, %2;" : "=r"(d) : "r"(a), "r"(b));
    return d;
}
__device__ __forceinline__ void split2pack(float x, float y, uint32_t& hi, uint32_t& lo) {
    __nv_bfloat16 hx = __float2bfloat16_rn(x);
    __nv_bfloat16 hy = __float2bfloat16_rn(y);
    __nv_bfloat16 lx = __float2bfloat16_rn(x - __bfloat162float(hx));
    __nv_bfloat16 ly = __float2bfloat16_rn(y - __bfloat162float(hy));
    hi = (uint32_t)__bfloat16_as_ushort(hx) | ((uint32_t)__bfloat16_as_ushort(hy) << 16);
    lo = (uint32_t)__bfloat16_as_ushort(lx) | ((uint32_t)__bfloat16_as_ushort(ly) << 16);
}
__device__ __forceinline__ void split2pack_f16(float x, float y, uint32_t& hi, uint32_t& lo) {
    __half hx = __float2half_rn(x);
    __half hy = __float2half_rn(y);
    __half lx = __float2half_rn(x - __half2float(hx));
    __half ly = __float2half_rn(y - __half2float(hy));
    hi = (uint32_t)__half_as_ushort(hx) | ((uint32_t)__half_as_ushort(hy) << 16);
    lo = (uint32_t)__half_as_ushort(lx) | ((uint32_t)__half_as_ushort(ly) << 16);
}
__device__ __forceinline__ uint32_t packh2(float x, float y) {
    __half2 h = __floats2half2_rn(x, y);
    return *(uint32_t*)&h;
}

// ---------------- fused prep: all converts in ONE launch ---------------------
#define N4X (BIG/4)
#define N4W (HIDDEN*HIDDEN/4)
#define N4G (2*HIDDEN*HIDDEN/4)
#define N4TOT (3*N4X + 4*N4W + N4G)

__device__ __forceinline__ void cvt4(const float* src, __half* dst, int i) {
    float4 v = ((const float4*)src)[i];
    ((__half2*)dst)[i*2]     = __floats2half2_rn(v.x, v.y);
    ((__half2*)dst)[i*2 + 1] = __floats2half2_rn(v.z, v.w);
}

__global__ __launch_bounds__(256) void prep_all(
    const float* __restrict__ x,  const float* __restrict__ spk,
    const float* __restrict__ mp, const float* __restrict__ Wq,
    const float* __restrict__ Wk, const float* __restrict__ Wv,
    const float* __restrict__ Wo, const float* __restrict__ Wg,
    __half* __restrict__ xh,  __half* __restrict__ xl,
    __half* __restrict__ spkf, __half* __restrict__ mpf,
    __half* __restrict__ Wqf, __half* __restrict__ Wkf,
    __half* __restrict__ Wvf, __half* __restrict__ Wof,
    __half* __restrict__ Wgf)
{
    int i = blockIdx.x * blockDim.x + threadIdx.x;
    if (i >= N4TOT) return;
    if (i < N4X) {
        float4 v = ((const float4*)x)[i];
        uint2 hi, lo;
        split2pack_f16(v.x, v.y, hi.x, lo.x);
        split2pack_f16(v.z, v.w, hi.y, lo.y);
        ((uint2*)xh)[i] = hi;
        ((uint2*)xl)[i] = lo;
        return;
    }
    i -= N4X;
    if (i < N4X) { cvt4(spk, spkf, i); return; }
    i -= N4X;
    if (i < N4X) { cvt4(mp, mpf, i); return; }
    i -= N4X;
    if (i < N4W) { cvt4(Wq, Wqf, i); return; }
    i -= N4W;
    if (i < N4W) { cvt4(Wk, Wkf, i); return; }
    i -= N4W;
    if (i < N4W) { cvt4(Wv, Wvf, i); return; }
    i -= N4W;
    if (i < N4W) { cvt4(Wo, Wof, i); return; }
    i -= N4W;
    cvt4(Wg, Wgf, i);
}

// ---------------- per-(b,h,ktile) gated-V column sums (fp16 V) ---------------
__global__ __launch_bounds__(64) void vsum_kernel(
    const __half* __restrict__ vf_g, float* __restrict__ vsum)
{
    const int d = threadIdx.x;
    const int t = blockIdx.x, h = blockIdx.y, b = blockIdx.z;
    const size_t base = ((size_t)(b * SSEQ + t * 64)) * HIDDEN + h * HDIM + d;
    float s = 0.0f;
#pragma unroll 8
    for (int r = 0; r < 64; ++r)
        s += __half2float(vf_g[base + (size_t)r * HIDDEN]);
    vsum[(((size_t)b * NHEADS + h) * 16 + t) * HDIM + d] = s;
}

// ---------------------------------------------------------------------------
// Fused QKV projection GEMM: ONE launch, gridDim.z = 3 (0:Q, 1:K, 2:V).
// Q/K: fp16 2-term.  V: fp16 1-term.  3-stage cp.async, 2 CTAs/SM.
// ---------------------------------------------------------------------------
#define BKP      40
#define ARR_B    (128*BKP*2)          // 10240
#define STAGE_Q  (3*ARR_B)            // 30720
#define GEMMQ_SMEM (3*STAGE_Q)        // 92160

__global__ __launch_bounds__(256, 2) void gemm_qkv_fused(
    const __half* __restrict__ Ah_g, const __half* __restrict__ Al_g,
    const __half* __restrict__ WqB, const __half* __restrict__ WkB,
    const __half* __restrict__ WvB,
    const float* __restrict__ bq, const float* __restrict__ bk,
    const float* __restrict__ bv, const float* __restrict__ mpE,
    __nv_bfloat16* __restrict__ qh_o, __nv_bfloat16* __restrict__ ql_o,
    __nv_bfloat16* __restrict__ kh_o, __nv_bfloat16* __restrict__ kl_o,
    __half* __restrict__ vf_o)
{
    extern __shared__ __align__(128) char smem[];
    const uint32_t sbase = smem_to_u32(smem);
    const int tid = threadIdx.x, wid = tid >> 5, lane = tid & 31;
    const int m0 = blockIdx.y * 128, n0 = blockIdx.x * 128;
    const int z = blockIdx.z;
    const int K = HIDDEN, N = HIDDEN;
    const int NCH = K >> 5;

    const __half* Bm   = (z == 0) ? WqB : (z == 1) ? WkB : WvB;
    const float*  bias = (z == 0) ? bq  : (z == 1) ? bk  : bv;
    const bool two_term = (z != 2);

    const int wm = (wid >> 1) * 32;
    const int wn = (wid & 1) * 64;

    float acc[2][8][4];
#pragma unroll
    for (int mt = 0; mt < 2; mt++)
#pragma unroll
        for (int nt = 0; nt < 8; nt++)
#pragma unroll
            for (int j = 0; j < 4; j++) acc[mt][nt][j] = 0.0f;

    auto fill = [&](int c) {
        const uint32_t st = sbase + (uint32_t)(c % 3) * STAGE_Q;
        const int k0 = c * 32;
#pragma unroll
        for (int i = 0; i < 2; ++i) {
            const int s = tid + i * 256;
            const int row = s >> 2, q = s & 3;
            const uint32_t d = st + (uint32_t)(row * 80 + q * 16);
            const size_t ga = ((size_t)(m0 + row) * K + k0 + q * 8) * 2;
            cp16(d,           (const char*)Ah_g + ga);
            if (two_term) cp16(d + ARR_B, (const char*)Al_g + ga);
            const size_t gb = ((size_t)(n0 + row) * K + k0 + q * 8) * 2;
            cp16(d + 2*ARR_B, (const char*)Bm + gb);
        }
        cp_commit();
    };

    const uint32_t a_lane_off = (uint32_t)((lane & 15) * (BKP * 2) + (lane >> 4) * 16);
    const uint32_t b_lane_off = (uint32_t)(((lane & 7) + ((lane >> 4) << 3)) * (BKP * 2)
                                           + ((lane >> 3) & 1) * 16);

    auto compute_chunk = [&](int c) {
        const uint32_t b = sbase + (uint32_t)(c % 3) * STAGE_Q;
#pragma unroll
        for (int ks = 0; ks < 2; ++ks) {
            const uint32_t koffb = (uint32_t)(ks * 32);
            uint32_t ah[2][4], al[2][4];
#pragma unroll
            for (int mt = 0; mt < 2; ++mt) {
                const uint32_t off = (uint32_t)((wm + mt * 16) * (BKP * 2)) + a_lane_off + koffb;
                ldsm_x4(ah[mt], b + off);
                if (two_term) ldsm_x4(al[mt], b + ARR_B + off);
            }
            uint32_t bh[8][2];
#pragma unroll
            for (int np = 0; np < 4; ++np) {
                const uint32_t off = (uint32_t)((wn + np * 16) * (BKP * 2)) + b_lane_off + koffb;
                uint32_t r4[4];
                ldsm_x4(r4, b + 2*ARR_B + off);
                bh[np*2][0] = r4[0]; bh[np*2][1] = r4[1];
                bh[np*2+1][0] = r4[2]; bh[np*2+1][1] = r4[3];
            }
#pragma unroll
            for (int mt = 0; mt < 2; ++mt)
#pragma unroll
                for (int nt = 0; nt < 8; ++nt) {
                    mma_f16(acc[mt][nt], ah[mt], bh[nt]);
                    if (two_term) mma_f16(acc[mt][nt], al[mt], bh[nt]);
                }
        }
    };

    fill(0);
    fill(1);
    for (int c = 0; c < NCH; ++c) {
        if (c < NCH - 1) cp_wait<1>(); else cp_wait<0>();
        __syncthreads();
        if (c + 2 < NCH) fill(c + 2);
        compute_chunk(c);
    }

    __nv_bfloat16* Ch = (z == 0) ? qh_o : kh_o;
    __nv_bfloat16* Cl = (z == 0) ? ql_o : kl_o;

#pragma unroll
    for (int mt = 0; mt < 2; ++mt) {
        const int m = m0 + wm + mt * 16 + (lane >> 2);
#pragma unroll
        for (int nt = 0; nt < 8; ++nt) {
            const int n = n0 + wn + nt * 8 + (lane & 3) * 2;
            const float2 bv2 = *(const float2*)(bias + n);
#pragma unroll
            for (int half = 0; half < 2; ++half) {
                const size_t off = (size_t)(m + half * 8) * N + n;
                float v0 = acc[mt][nt][half*2 + 0] + bv2.x;
                float v1 = acc[mt][nt][half*2 + 1] + bv2.y;
                if (z == 2) {
                    float2 e = *(const float2*)(mpE + off);
                    v0 *= sigmoidf_(e.x); v1 *= sigmoidf_(e.y);
                    *(uint32_t*)((char*)vf_o + off * 2) = packh2(v0, v1);
                } else {
                    uint32_t hi, lo;
                    split2pack(v0, v1, hi, lo);
                    *(uint32_t*)((char*)Ch + off * 2) = hi;
                    *(uint32_t*)((char*)Cl + off * 2) = lo;
                }
            }
        }
    }
}

// ---------------------------------------------------------------------------
// Single-pass fp16 NT GEMM (gate + output), 3-stage, 2 CTAs/SM.
// EPI 2: Cf = Ef * sigmoid(v)  (Ef fp16 = attention ctx).  EPI 0: C = v (fp32).
// ---------------------------------------------------------------------------
#define STAGE_H  (2*ARR_B)            // 20480
#define GEMMH_SMEM (3*STAGE_H)        // 61440

template<int EPI>
__global__ __launch_bounds__(256, 2) void gemm_h(
    const __half* __restrict__ A1, const __half* __restrict__ A2,
    int K1, int K,
    const __half* __restrict__ Bm,
    const float* __restrict__ bias, const __half* __restrict__ Ef,
    float* __restrict__ C, __half* __restrict__ Cf,
    int M, int N)
{
    extern __shared__ __align__(128) char smem[];
    const uint32_t sbase = smem_to_u32(smem);
    const int tid = threadIdx.x, wid = tid >> 5, lane = tid & 31;
    const int m0 = blockIdx.y * 128, n0 = blockIdx.x * 128;
    const int NCH = K >> 5;

    const int wm = (wid >> 1) * 32;
    const int wn = (wid & 1) * 64;

    float acc[2][8][4];
#pragma unroll
    for (int mt = 0; mt < 2; mt++)
#pragma unroll
        for (int nt = 0; nt < 8; nt++)
#pragma unroll
            for (int j = 0; j < 4; j++) acc[mt][nt][j] = 0.0f;

    auto fill = [&](int c) {
        const uint32_t st = sbase + (uint32_t)(c % 3) * STAGE_H;
        const int k0 = c * 32;
        const __half* Ap; int lda, koff;
        if (k0 < K1) { Ap = A1; lda = K1;     koff = k0; }
        else         { Ap = A2; lda = K - K1; koff = k0 - K1; }
#pragma unroll
        for (int i = 0; i < 2; ++i) {
            const int s = tid + i * 256;
            const int row = s >> 2, q = s & 3;
            const uint32_t d = st + (uint32_t)(row * 80 + q * 16);
            const size_t ga = ((size_t)(m0 + row) * lda + koff + q * 8) * 2;
            cp16(d,           (const char*)Ap + ga);
            const size_t gb = ((size_t)(n0 + row) * K + k0 + q * 8) * 2;
            cp16(d + ARR_B,   (const char*)Bm + gb);
        }
        cp_commit();
    };

    const uint32_t a_lane_off = (uint32_t)((lane & 15) * (BKP * 2) + (lane >> 4) * 16);
    const uint32_t b_lane_off = (uint32_t)(((lane & 7) + ((lane >> 4) << 3)) * (BKP * 2)
                                           + ((lane >> 3) & 1) * 16);

    auto compute_chunk = [&](int c) {
        const uint32_t b = sbase + (uint32_t)(c % 3) * STAGE_H;
#pragma unroll
        for (int ks = 0; ks < 2; ++ks) {
            const uint32_t koffb = (uint32_t)(ks * 32);
            uint32_t ah[2][4];
#pragma unroll
            for (int mt = 0; mt < 2; ++mt) {
                const uint32_t off = (uint32_t)((wm + mt * 16) * (BKP * 2)) + a_lane_off + koffb;
                ldsm_x4(ah[mt], b + off);
            }
            uint32_t bh[8][2];
#pragma unroll
            for (int np = 0; np < 4; ++np) {
                const uint32_t off = (uint32_t)((wn + np * 16) * (BKP * 2)) + b_lane_off + koffb;
                uint32_t r4[4];
                ldsm_x4(r4, b + ARR_B + off);
                bh[np*2][0] = r4[0]; bh[np*2][1] = r4[1];
                bh[np*2+1][0] = r4[2]; bh[np*2+1][1] = r4[3];
            }
#pragma unroll
            for (int mt = 0; mt < 2; ++mt)
#pragma unroll
                for (int nt = 0; nt < 8; ++nt)
                    mma_f16(acc[mt][nt], ah[mt], bh[nt]);
        }
    };

    fill(0);
    fill(1);
    for (int c = 0; c < NCH; ++c) {
        if (c < NCH - 1) cp_wait<1>(); else cp_wait<0>();
        __syncthreads();
        if (c + 2 < NCH) fill(c + 2);
        compute_chunk(c);
    }

#pragma unroll
    for (int mt = 0; mt < 2; ++mt) {
        const int m = m0 + wm + mt * 16 + (lane >> 2);
#pragma unroll
        for (int nt = 0; nt < 8; ++nt) {
            const int n = n0 + wn + nt * 8 + (lane & 3) * 2;
            const float2 bv = *(const float2*)(bias + n);
#pragma unroll
            for (int half = 0; half < 2; ++half) {
                const size_t off = (size_t)(m + half * 8) * N + n;
                float v0 = acc[mt][nt][half*2 + 0] + bv.x;
                float v1 = acc[mt][nt][half*2 + 1] + bv.y;
                if (EPI == 2) {
                    __half2 e2 = *(const __half2*)(Ef + off);
                    float2 e = __half22float2(e2);
                    v0 = e.x * sigmoidf_(v0); v1 = e.y * sigmoidf_(v1);
                    *(__half2*)(Cf + off) = __floats2half2_rn(v0, v1);
                } else {
                    *(float2*)(C + off) = make_float2(v0, v1);
                }
            }
        }
    }
}

// ---------------------------------------------------------------------------
// Tensor-core flash attention, decay-window tile skipping (dt<96).
// 128-thread CTAs, 64-row q tiles, 3-stage pipeline, 2 CTAs/SM (221 KB smem).
// Mask exps via geometric recurrence. fp16-only ctx output.
// ---------------------------------------------------------------------------
#define KROW    144
#define ARR_A   (64*KROW)              // 9216
#define STAGE_A (4*ARR_A)              // 36864
#define ATTN_SMEM (3*STAGE_A)          // 110592 -> 2 CTAs/SM (221184 <= 228K)
#define SCALE2  0x3E003E00u            // bf16x2 {0.125, 0.125}
#define HSCALE2 0x30003000u            // f16x2  {0.125, 0.125}

__global__ __launch_bounds__(128, 2) void attn_mma(
    const __nv_bfloat16* __restrict__ qh_g, const __nv_bfloat16* __restrict__ ql_g,
    const __nv_bfloat16* __restrict__ kh_g, const __nv_bfloat16* __restrict__ kl_g,
    const __half* __restrict__ vf_g, const __half* __restrict__ skf_g,
    const float* __restrict__ tau, const float* __restrict__ vsum,
    __half* __restrict__ ctxf)
{
    extern __shared__ __align__(128) char smem[];
    const uint32_t sb = smem_to_u32(smem);
    const int tid = threadIdx.x, wid = tid >> 5, lane = tid & 31;
    const int lane4 = lane & 3, laneq = lane >> 2;
    const int h = blockIdx.y, b = blockIdx.z;
    const int q0 = blockIdx.x * 64;
    const float inv_tau = 1.0f / tau[h];
    const float r8  = __expf(8.0f * inv_tau);
    const float r8i = __expf(-8.0f * inv_tau);
    const float e1  = __expf(inv_tau);
    const float e1i = __expf(-inv_tau);

    const int lo = q0 - 158;
    const int ktmin = lo <= 0 ? 0 : ((lo + 63) >> 6);
    const int ktmax_ = (q0 + 158) >> 6;
    const int ktmax = ktmax_ > 15 ? 15 : ktmax_;

    const int ti0 = q0 + wid * 16 + laneq;
    const int ti1 = ti0 + 8;
    const size_t r0b = (size_t)(b * SSEQ + ti0) * HIDDEN + h * HDIM;
    const size_t r1b = (size_t)(b * SSEQ + ti1) * HIDDEN + h * HDIM;

    uint32_t qh[4][4], ql[4][4], sqf[4][4];
    {
        const char* qhp = (const char*)qh_g;
        const char* qlp = (const char*)ql_g;
        const char* sfp = (const char*)skf_g;
#pragma unroll
        for (int ks = 0; ks < 4; ++ks) {
            const int kc = ks * 16 + lane4 * 2;
            const size_t o00 = (r0b + kc) * 2, o10 = (r1b + kc) * 2;
            const size_t o01 = o00 + 16,       o11 = o10 + 16;
            qh[ks][0] = mul_bf16x2(*(const uint32_t*)(qhp + o00), SCALE2);
            qh[ks][1] = mul_bf16x2(*(const uint32_t*)(qhp + o10), SCALE2);
            qh[ks][2] = mul_bf16x2(*(const uint32_t*)(qhp + o01), SCALE2);
            qh[ks][3] = mul_bf16x2(*(const uint32_t*)(qhp + o11), SCALE2);
            ql[ks][0] = mul_bf16x2(*(const uint32_t*)(qlp + o00), SCALE2);
            ql[ks][1] = mul_bf16x2(*(const uint32_t*)(qlp + o10), SCALE2);
            ql[ks][2] = mul_bf16x2(*(const uint32_t*)(qlp + o01), SCALE2);
            ql[ks][3] = mul_bf16x2(*(const uint32_t*)(qlp + o11), SCALE2);
            sqf[ks][0] = mul_f16x2(*(const uint32_t*)(sfp + o00), HSCALE2);
            sqf[ks][1] = mul_f16x2(*(const uint32_t*)(sfp + o10), HSCALE2);
            sqf[ks][2] = mul_f16x2(*(const uint32_t*)(sfp + o01), HSCALE2);
            sqf[ks][3] = mul_f16x2(*(const uint32_t*)(sfp + o11), HSCALE2);
        }
    }

    float m0r = -1e30f, m1r = -1e30f, l0r = 0.0f, l1r = 0.0f;
    float o[8][4];
#pragma unroll
    for (int nt = 0; nt < 8; nt++)
#pragma unroll
        for (int j = 0; j < 4; j++) o[nt][j] = 0.0f;

    auto fill_tile = [&](int kt) {
        const uint32_t st = sb + (uint32_t)(kt % 3) * STAGE_A;
        const size_t base = ((size_t)(b * SSEQ + kt * 64)) * HIDDEN + h * HDIM;
#pragma unroll
        for (int i = 0; i < 4; ++i) {
            const int s = tid + i * 128;
            const int row = s >> 3, q = s & 7;
            const size_t g2 = (base + (size_t)row * HIDDEN + q * 8) * 2;
            const uint32_t d = st + (uint32_t)(row * KROW + q * 16);
            cp16(d + 0*ARR_A, (const char*)kh_g  + g2);
            cp16(d + 1*ARR_A, (const char*)kl_g  + g2);
            cp16(d + 2*ARR_A, (const char*)skf_g + g2);
            cp16(d + 3*ARR_A, (const char*)vf_g  + g2);
        }
        cp_commit();
    };

    const uint32_t b_off = (uint32_t)(((lane & 7) + ((lane >> 4) << 3)) * KROW
                                      + ((lane >> 3) & 1) * 16);
    const uint32_t v_off = (uint32_t)(((lane & 7) + ((lane >> 3) & 1) * 8) * KROW
                                      + ((lane >> 4) & 1) * 16);
    const float ti0f = (float)ti0, ti1f = (float)ti1;

    fill_tile(ktmin);
    if (ktmin + 1 <= ktmax) fill_tile(ktmin + 1);
    for (int kt = ktmin; kt <= ktmax; ++kt) {
        if (kt < ktmax) cp_wait<1>(); else cp_wait<0>();
        __syncthreads();
        if (kt + 2 <= ktmax) fill_tile(kt + 2);

        const uint32_t st = sb + (uint32_t)(kt % 3) * STAGE_A;
        const int k0 = kt * 64;

        float s[8][4], sp[8][4];
#pragma unroll
        for (int nt = 0; nt < 8; nt++)
#pragma unroll
            for (int j = 0; j < 4; j++) { s[nt][j] = 0.0f; sp[nt][j] = 0.0f; }

#pragma unroll
        for (int ks = 0; ks < 4; ++ks) {
            const uint32_t kb = (uint32_t)(ks * 32);
#pragma unroll
            for (int n8 = 0; n8 < 4; ++n8) {
                const uint32_t off = (uint32_t)(n8 * 16 * KROW) + b_off + kb;
                uint32_t rh[4], rl[4];
                ldsm_x4(rh, st + 0*ARR_A + off);
                ldsm_x4(rl, st + 1*ARR_A + off);
                mma_bf16(s[2*n8],   qh[ks], &rh[0]);
                mma_bf16(s[2*n8],   qh[ks], &rl[0]);
                mma_bf16(s[2*n8],   ql[ks], &rh[0]);
                mma_bf16(s[2*n8+1], qh[ks], &rh[2]);
                mma_bf16(s[2*n8+1], qh[ks], &rl[2]);
                mma_bf16(s[2*n8+1], ql[ks], &rh[2]);
                uint32_t rs[4];
                ldsm_x4(rs, st + 2*ARR_A + off);
                mma_f16(sp[2*n8],   sqf[ks], &rs[0]);
                mma_f16(sp[2*n8+1], sqf[ks], &rs[2]);
            }
        }

        // ---- mask via geometric recurrence + online softmax ----
        {
            const float d00 = (float)(k0 + lane4 * 2) - ti0f;
            const float d10 = (float)(k0 + lane4 * 2) - ti1f;
            float u0 = __expf(d00 * inv_tau), v0 = __expf(-d00 * inv_tau);
            float u1 = __expf(d10 * inv_tau), v1 = __expf(-d10 * inv_tau);
            float u0b = u0 * e1, v0b = v0 * e1i;
            float u1b = u1 * e1, v1b = v1 * e1i;
            float rmax0 = -1e30f, rmax1 = -1e30f;
#pragma unroll
            for (int nt = 0; nt < 8; ++nt) {
                const float e00 = fminf(u0, v0);
                const float e01 = fminf(u0b, v0b);
                const float e10 = fminf(u1, v1);
                const float e11 = fminf(u1b, v1b);
                u0 *= r8; v0 *= r8i; u0b *= r8; v0b *= r8i;
                u1 *= r8; v1 *= r8i; u1b *= r8; v1b *= r8i;
                s[nt][0] = s[nt][0] * e00 * (1.0f + sp[nt][0]);
                s[nt][1] = s[nt][1] * e01 * (1.0f + sp[nt][1]);
                s[nt][2] = s[nt][2] * e10 * (1.0f + sp[nt][2]);
                s[nt][3] = s[nt][3] * e11 * (1.0f + sp[nt][3]);
                rmax0 = fmaxf(rmax0, fmaxf(s[nt][0], s[nt][1]));
                rmax1 = fmaxf(rmax1, fmaxf(s[nt][2], s[nt][3]));
            }
            rmax0 = fmaxf(rmax0, __shfl_xor_sync(0xffffffffu, rmax0, 1));
            rmax0 = fmaxf(rmax0, __shfl_xor_sync(0xffffffffu, rmax0, 2));
            rmax1 = fmaxf(rmax1, __shfl_xor_sync(0xffffffffu, rmax1, 1));
            rmax1 = fmaxf(rmax1, __shfl_xor_sync(0xffffffffu, rmax1, 2));
            const float mn0 = fmaxf(m0r, rmax0), mn1 = fmaxf(m1r, rmax1);
            const float c0 = __expf(m0r - mn0), c1 = __expf(m1r - mn1);
            float ls0 = 0.0f, ls1 = 0.0f;
#pragma unroll
            for (int nt = 0; nt < 8; ++nt) {
                float p;
                p = __expf(s[nt][0] - mn0); s[nt][0] = p; ls0 += p;
                p = __expf(s[nt][1] - mn0); s[nt][1] = p; ls0 += p;
                p = __expf(s[nt][2] - mn1); s[nt][2] = p; ls1 += p;
                p = __expf(s[nt][3] - mn1); s[nt][3] = p; ls1 += p;
            }
            ls0 += __shfl_xor_sync(0xffffffffu, ls0, 1);
            ls0 += __shfl_xor_sync(0xffffffffu, ls0, 2);
            ls1 += __shfl_xor_sync(0xffffffffu, ls1, 1);
            ls1 += __shfl_xor_sync(0xffffffffu, ls1, 2);
            l0r = l0r * c0 + ls0;  m0r = mn0;
            l1r = l1r * c1 + ls1;  m1r = mn1;
#pragma unroll
            for (int nt = 0; nt < 8; ++nt) {
                o[nt][0] *= c0; o[nt][1] *= c0;
                o[nt][2] *= c1; o[nt][3] *= c1;
            }
        }

#pragma unroll
        for (int ks = 0; ks < 4; ++ks) {
            uint32_t ph[4];
            ph[0] = packh2(s[2*ks][0],   s[2*ks][1]);
            ph[1] = packh2(s[2*ks][2],   s[2*ks][3]);
            ph[2] = packh2(s[2*ks+1][0], s[2*ks+1][1]);
            ph[3] = packh2(s[2*ks+1][2], s[2*ks+1][3]);
            const uint32_t roff = (uint32_t)(ks * 16 * KROW) + v_off;
#pragma unroll
            for (int n8 = 0; n8 < 4; ++n8) {
                uint32_t vfr[4];
                ldsm_x4_trans(vfr, st + 3*ARR_A + roff + (uint32_t)(n8 * 32));
                mma_f16(o[2*n8],   ph, &vfr[0]);
                mma_f16(o[2*n8+1], ph, &vfr[2]);
            }
        }
    }

    {
        float2 fsum[8];
#pragma unroll
        for (int nt = 0; nt < 8; ++nt) { fsum[nt].x = 0.0f; fsum[nt].y = 0.0f; }
        const float2* vsbase = (const float2*)(vsum + (((size_t)b * NHEADS + h) * 16) * HDIM);
        for (int t = 0; t < 16; ++t) {
            if (t >= ktmin && t <= ktmax) continue;
            const float2* vs = vsbase + t * (HDIM / 2);
#pragma unroll
            for (int nt = 0; nt < 8; ++nt) {
                float2 v = vs[nt * 4 + lane4];
                fsum[nt].x += v.x; fsum[nt].y += v.y;
            }
        }
        const float nfar = (float)(64 * (16 - (ktmax - ktmin + 1)));
        const float mf0 = fmaxf(m0r, 0.0f), mf1 = fmaxf(m1r, 0.0f);
        const float c0 = __expf(m0r - mf0), c1 = __expf(m1r - mf1);
        const float e0 = __expf(-mf0),      e1f = __expf(-mf1);
        l0r = l0r * c0 + nfar * e0;
        l1r = l1r * c1 + nfar * e1f;
#pragma unroll
        for (int nt = 0; nt < 8; ++nt) {
            o[nt][0] = o[nt][0] * c0 + e0 * fsum[nt].x;
            o[nt][1] = o[nt][1] * c0 + e0 * fsum[nt].y;
            o[nt][2] = o[nt][2] * c1 + e1f * fsum[nt].x;
            o[nt][3] = o[nt][3] * c1 + e1f * fsum[nt].y;
        }
    }

    const float inv0 = 1.0f / l0r, inv1 = 1.0f / l1r;
#pragma unroll
    for (int nt = 0; nt < 8; ++nt) {
        const int d = nt * 8 + lane4 * 2;
        *(__half2*)(ctxf + r0b + d) = __floats2half2_rn(o[nt][0] * inv0, o[nt][1] * inv0);
        *(__half2*)(ctxf + r1b + d) = __floats2half2_rn(o[nt][2] * inv1, o[nt][3] * inv1);
    }
}

// ---------------------------------------------------------------------------
extern "C" void kernel_launch(void* const* d_in, const int* in_sizes, int n_in,
                              void* d_out, int out_size)
{
    const float* x   = (const float*)d_in[0];
    const float* spk = (const float*)d_in[1];
    const float* mp  = (const float*)d_in[2];
    const float* Wq  = (const float*)d_in[3];
    const float* bq  = (const float*)d_in[4];
    const float* Wk  = (const float*)d_in[5];
    const float* bk  = (const float*)d_in[6];
    const float* Wv  = (const float*)d_in[7];
    const float* bv  = (const float*)d_in[8];
    const float* Wo  = (const float*)d_in[9];
    const float* bo  = (const float*)d_in[10];
    const float* tau = (const float*)d_in[11];
    const float* Wg  = (const float*)d_in[12];
    const float* bg  = (const float*)d_in[13];
    float* out = (float*)d_out;

    __half *xh16, *xl16, *Wqf, *Wkf, *Wvf;
    __nv_bfloat16 *qh, *ql, *kh, *kl;
    __half *spkf, *vf, *mpf, *ctxf, *cgf, *Wgf, *Wof;
    float *vsum;
    cudaGetSymbolAddress((void**)&xh16, g_xh16); cudaGetSymbolAddress((void**)&xl16, g_xl16);
    cudaGetSymbolAddress((void**)&qh,   g_qh);   cudaGetSymbolAddress((void**)&ql,   g_ql);
    cudaGetSymbolAddress((void**)&kh,   g_kh);   cudaGetSymbolAddress((void**)&kl,   g_kl);
    cudaGetSymbolAddress((void**)&Wqf,  g_Wqf);
    cudaGetSymbolAddress((void**)&Wkf,  g_Wkf);
    cudaGetSymbolAddress((void**)&Wvf,  g_Wvf);
    cudaGetSymbolAddress((void**)&spkf, g_spkf); cudaGetSymbolAddress((void**)&vf,   g_vf);
    cudaGetSymbolAddress((void**)&mpf,  g_mpf);  cudaGetSymbolAddress((void**)&ctxf, g_ctxf);
    cudaGetSymbolAddress((void**)&cgf,  g_cgf);
    cudaGetSymbolAddress((void**)&Wgf,  g_Wgf);  cudaGetSymbolAddress((void**)&Wof,  g_Wof);
    cudaGetSymbolAddress((void**)&vsum, g_vsum);

    cudaFuncSetAttribute(gemm_qkv_fused, cudaFuncAttributeMaxDynamicSharedMemorySize, GEMMQ_SMEM);
    cudaFuncSetAttribute(gemm_h<0>,  cudaFuncAttributeMaxDynamicSharedMemorySize, GEMMH_SMEM);
    cudaFuncSetAttribute(gemm_h<2>,  cudaFuncAttributeMaxDynamicSharedMemorySize, GEMMH_SMEM);
    cudaFuncSetAttribute(attn_mma,   cudaFuncAttributeMaxDynamicSharedMemorySize, ATTN_SMEM);

    // ---- one fused prep launch ----
    prep_all<<<(N4TOT + 255) / 256, 256>>>(x, spk, mp, Wq, Wk, Wv, Wo, Wg,
                                           xh16, xl16, spkf, mpf,
                                           Wqf, Wkf, Wvf, Wof, Wgf);

    dim3 tb(256);

    // ---- fused QKV projections: one launch, z = {Q, K, V} ----
    dim3 gq(HIDDEN / 128, MTOT / 128, 3);   // (8, 32, 3)
    gemm_qkv_fused<<<gq, tb, GEMMQ_SMEM>>>(xh16, xl16, Wqf, Wkf, Wvf,
                                           bq, bk, bv, mp,
                                           qh, ql, kh, kl, vf);

    dim3 gv(16, NHEADS, BB);
    vsum_kernel<<<gv, 64>>>(vf, vsum);

    // ---- attention: 128-thread CTAs, 64-row q tiles, 3-stage, 2 CTAs/SM ----
    dim3 ga(SSEQ / 64, NHEADS, BB);         // (16,16,4) = 1024
    attn_mma<<<ga, dim3(128), ATTN_SMEM>>>(qh, ql, kh, kl, vf, spkf,
                                           tau, vsum, ctxf);

    dim3 gb(HIDDEN / 128, MTOT / 128);      // (8, 32)
    // gate: cg = ctxf * sigmoid([ctxf, mp] @ Wg^T + bg)   (gating factor fp16)
    gemm_h<2><<<gb, tb, GEMMH_SMEM>>>(ctxf, mpf, HIDDEN, 2 * HIDDEN,
                                      Wgf, bg, ctxf, nullptr, cgf, MTOT, HIDDEN);
    // out = cg @ Wo^T + bo
    gemm_h<0><<<gb, tb, GEMMH_SMEM>>>(cgf, nullptr, HIDDEN, HIDDEN,
                                      Wof, bo, nullptr, out, nullptr, MTOT, HIDDEN);
}